// round 14
// baseline (speedup 1.0000x reference)
#include <cuda_runtime.h>
#include <cuda_bf16.h>
#include <math.h>

#define NN 40000
#define EE 320000
#define FIN 128
#define HH 4
#define HC 256
#define OUTC 64
#define SCB ((NN + 255) / 256)   // 157

// ---------------- scratch ----------------
__device__ int g_pre[NN + 2 * SCB];
__device__ __align__(16) int g_src[EE];
__device__ __align__(16) int g_dst[EE];
__device__ int g_rowstart[NN + 1];
__device__ int g_cursor[NN];
__device__ __align__(16) int g_csr_src[EE];
__device__ __align__(16) float g_h[(size_t)NN * HC];
__device__ __align__(16) float g_gat[(size_t)NN * HC];
__device__ __align__(16) float g_l1[(size_t)NN * HC];
__device__ __align__(16) float g_l2[(size_t)NN * HC];
__device__ __align__(16) float g_es[NN * HH];
__device__ __align__(16) float g_ed[NN * HH];
__device__ __align__(16) float g_alpha[(size_t)EE * HH];
__device__ float g_bnsum[2 * HC];
__device__ __align__(16) __nv_bfloat16 g_w1t_hi[HC * FIN];
__device__ __align__(16) __nv_bfloat16 g_w1t_lo[HC * FIN];
__device__ __align__(16) __nv_bfloat16 g_w2t_hi[HC * HC];
__device__ __align__(16) __nv_bfloat16 g_w2t_lo[HC * HC];
__device__ __align__(16) __nv_bfloat16 g_w3t_hi[OUTC * HC];
__device__ __align__(16) __nv_bfloat16 g_w3t_lo[OUTC * HC];

// ---------------- helpers ----------------
__device__ __forceinline__ unsigned smem_u32(const void* p) {
    unsigned r;
    asm("{ .reg .u64 t; cvta.to.shared.u64 t, %1; cvt.u32.u64 %0, t; }" : "=r"(r) : "l"(p));
    return r;
}
__device__ __forceinline__ unsigned pack2(float a, float b) {
    __nv_bfloat162 t = __floats2bfloat162_rn(a, b);
    return *reinterpret_cast<unsigned*>(&t);
}
__device__ __forceinline__ void ldsm4(unsigned* d, unsigned a) {
    asm volatile("ldmatrix.sync.aligned.m8n8.x4.shared.b16 {%0,%1,%2,%3}, [%4];"
                 : "=r"(d[0]), "=r"(d[1]), "=r"(d[2]), "=r"(d[3]) : "r"(a));
}
__device__ __forceinline__ void mma16816(float* c, const unsigned* a, const unsigned* b) {
    asm volatile(
        "mma.sync.aligned.m16n8k16.row.col.f32.bf16.bf16.f32 "
        "{%0,%1,%2,%3}, {%4,%5,%6,%7}, {%8,%9}, {%0,%1,%2,%3};"
        : "+f"(c[0]), "+f"(c[1]), "+f"(c[2]), "+f"(c[3])
        : "r"(a[0]), "r"(a[1]), "r"(a[2]), "r"(a[3]), "r"(b[0]), "r"(b[1]));
}
__device__ __forceinline__ void cp16(unsigned saddr, const void* gptr) {
    asm volatile("cp.async.cg.shared.global [%0], [%1], 16;" :: "r"(saddr), "l"(gptr));
}

// ---------------- preprocessing (detect merged into cvt) ----------------
__global__ void cvt_count_k(const void* __restrict__ idx) {
    __shared__ int is64s;
    if (threadIdx.x == 0) {
        const unsigned* buf = (const unsigned*)idx;
        int any = 0;
        #pragma unroll
        for (int i = 0; i < 64; i++) any |= (buf[2 * i + 1] != 0u);
        is64s = any ? 0 : 1;
    }
    __syncthreads();
    int e = blockIdx.x * blockDim.x + threadIdx.x;
    if (e >= EE) return;
    int s, d;
    if (is64s) {
        s = (int)((const long long*)idx)[e];
        d = (int)((const long long*)idx)[(long long)EE + e];
    } else {
        s = ((const int*)idx)[e];
        d = ((const int*)idx)[EE + e];
    }
    g_src[e] = s;
    g_dst[e] = d;
    atomicAdd(&g_pre[d], 1);
}
__global__ void scanfused_k() {
    int t = threadIdx.x, b = blockIdx.x;
    if (b == 0) { g_bnsum[t] = 0.f; g_bnsum[t + HC] = 0.f; }
    int i = b * 256 + t;
    int v = (i < NN) ? g_pre[i] : 0;
    int lane = t & 31, w = t >> 5;
    int x = v;
    #pragma unroll
    for (int d = 1; d < 32; d <<= 1) {
        int y = __shfl_up_sync(0xFFFFFFFFu, x, d);
        if (lane >= d) x += y;
    }
    __shared__ int ws[8];
    __shared__ int s_off;
    if (lane == 31) ws[w] = x;
    __syncthreads();
    if (t == 0) {
        int s = 0;
        #pragma unroll
        for (int j = 0; j < 8; j++) { s += ws[j]; ws[j] = s; }
        int total = s;
        int* part = g_pre + NN;
        int* pref = g_pre + NN + SCB;
        atomicExch(&part[b], total + 1);
        int run = 0;
        for (int j = b - 1; j >= 0;) {
            int pf = atomicAdd(&pref[j], 0);
            if (pf) { run += pf - 1; break; }
            int pt = atomicAdd(&part[j], 0);
            if (pt) { run += pt - 1; j--; }
        }
        atomicExch(&pref[b], run + total + 1);
        s_off = run;
    }
    __syncthreads();
    int incl = x + (w ? ws[w - 1] : 0);
    int off = s_off;
    if (i < NN) {
        int ex = off + incl - v;
        g_rowstart[i] = ex;
        g_cursor[i] = ex;
    }
    if (i == 0) g_rowstart[NN] = EE;
}
__global__ void fill_k() {
    int e = blockIdx.x * blockDim.x + threadIdx.x;
    if (e >= EE) return;
    int pos = atomicAdd(&g_cursor[g_dst[e]], 1);
    g_csr_src[pos] = g_src[e];
}

// ---------------- weight transpose + bf16 split (W1 alone; W2+W3 together) ----------------
__global__ void wconv1_k(const float* __restrict__ W1) {
    int idx = blockIdx.x * blockDim.x + threadIdx.x;
    if (idx >= FIN * HC) return;
    int k = idx / HC, n = idx % HC;
    float v = W1[idx];
    __nv_bfloat16 h = __float2bfloat16_rn(v);
    g_w1t_hi[(size_t)n * FIN + k] = h;
    g_w1t_lo[(size_t)n * FIN + k] = __float2bfloat16_rn(v - __bfloat162float(h));
}
__global__ void wconv23_k(const float* __restrict__ W2, const float* __restrict__ W3) {
    int gid = blockIdx.x * blockDim.x + threadIdx.x;
    const float* W;
    __nv_bfloat16 *Thi, *Tlo;
    int K, N, idx;
    if (gid < HC * HC) {
        W = W2; Thi = g_w2t_hi; Tlo = g_w2t_lo; K = HC; N = HC; idx = gid;
    } else if (gid < HC * HC + HC * OUTC) {
        W = W3; Thi = g_w3t_hi; Tlo = g_w3t_lo; K = HC; N = OUTC; idx = gid - HC * HC;
    } else return;
    int k = idx / N, n = idx % N;
    float v = W[idx];
    __nv_bfloat16 h = __float2bfloat16_rn(v);
    Thi[(size_t)n * K + k] = h;
    Tlo[(size_t)n * K + k] = __float2bfloat16_rn(v - __bfloat162float(h));
}

// ---------------- pipelined mma.sync split-bf16 GEMM (+ fused attention scores) ----------------
template <int KT, int NT, int NTILE, int WARPS_N, int JK, int SCORES>
__global__ __launch_bounds__(128 * WARPS_N, 2)
void mma_gemm_k(const float* __restrict__ A, const float* __restrict__ A2,
                const __nv_bfloat16* __restrict__ Bhi, const __nv_bfloat16* __restrict__ Blo,
                const float* __restrict__ bias, float* __restrict__ C,
                const float* __restrict__ asrc, const float* __restrict__ adst, int M) {
    constexpr int THREADS = 128 * WARPS_N;
    constexpr int WN = NTILE / WARPS_N;
    constexpr int NI = WN / 8;
    constexpr int LDA = 1024 / THREADS;
    constexpr int LDB = 8 * NTILE / THREADS;
    constexpr int CH = KT / 32;
    constexpr unsigned ABUF = 20480;
    constexpr unsigned BOFF = 2 * ABUF;
    constexpr unsigned BBUF = NTILE * 160;

    extern __shared__ char dynsm[];
    unsigned sbase = smem_u32(dynsm);
    int tid = threadIdx.x, lane = tid & 31, wid = tid >> 5;
    int wr = wid & 3, wc = wid >> 2;
    int rowBase = blockIdx.y * 128;
    int colBase = blockIdx.x * NTILE;
    float acc[2][NI][4] = {};
    float4 av[LDA], av2[LDA];

    auto loadA = [&](int c) {
        #pragma unroll
        for (int i = 0; i < LDA; i++) {
            int q = tid + i * THREADS;
            int r = q >> 3, cc = (q & 7) * 4;
            int grow = rowBase + r;
            av[i] = make_float4(0.f, 0.f, 0.f, 0.f);
            av2[i] = make_float4(0.f, 0.f, 0.f, 0.f);
            if (grow < M) {
                av[i] = *(const float4*)(A + (size_t)grow * KT + c * 32 + cc);
                if (JK) av2[i] = *(const float4*)(A2 + (size_t)grow * KT + c * 32 + cc);
            }
        }
    };
    auto storeA = [&](int buf) {
        #pragma unroll
        for (int i = 0; i < LDA; i++) {
            int q = tid + i * THREADS;
            int r = q >> 3, cc = (q & 7) * 4;
            float4 v = av[i];
            if (JK) {
                float4 w = av2[i];
                v.x = fmaxf(v.x, w.x); v.y = fmaxf(v.y, w.y);
                v.z = fmaxf(v.z, w.z); v.w = fmaxf(v.w, w.w);
            }
            float hx = __bfloat162float(__float2bfloat16_rn(v.x));
            float hy = __bfloat162float(__float2bfloat16_rn(v.y));
            float hz = __bfloat162float(__float2bfloat16_rn(v.z));
            float hw = __bfloat162float(__float2bfloat16_rn(v.w));
            unsigned off = buf * ABUF + (unsigned)(r * 40 + cc) * 2;
            *(uint2*)(dynsm + off) = make_uint2(pack2(hx, hy), pack2(hz, hw));
            *(uint2*)(dynsm + off + 10240) =
                make_uint2(pack2(v.x - hx, v.y - hy), pack2(v.z - hz, v.w - hw));
        }
    };
    auto loadB = [&](int c, int buf) {
        #pragma unroll
        for (int i = 0; i < LDB; i++) {
            int q = tid + i * THREADS;
            int hl = q / (4 * NTILE);
            int rem = q - hl * 4 * NTILE;
            int r = rem >> 2, seg = rem & 3;
            const __nv_bfloat16* src = hl ? Blo : Bhi;
            unsigned soff = BOFF + buf * BBUF + hl * (NTILE * 80) +
                            (unsigned)(r * 80 + seg * 16);
            cp16(sbase + soff, src + (size_t)(colBase + r) * KT + c * 32 + seg * 8);
        }
        asm volatile("cp.async.commit_group;");
    };
    auto compute = [&](int buf) {
        unsigned saA = sbase + buf * ABUF;
        unsigned saB = sbase + BOFF + buf * BBUF;
        #pragma unroll
        for (int kk = 0; kk < 32; kk += 16) {
            unsigned ah[2][4], al[2][4], bh[NI / 2][4], bl[NI / 2][4];
            #pragma unroll
            for (int mi = 0; mi < 2; mi++) {
                int row = wr * 32 + mi * 16 + (lane & 7) + ((lane & 8) ? 8 : 0);
                int col = kk + ((lane & 16) ? 8 : 0);
                ldsm4(ah[mi], saA + (unsigned)(row * 40 + col) * 2);
                ldsm4(al[mi], saA + 10240 + (unsigned)(row * 40 + col) * 2);
            }
            #pragma unroll
            for (int nb = 0; nb < NI / 2; nb++) {
                int row = wc * WN + nb * 16 + ((lane & 16) ? 8 : 0) + (lane & 7);
                int col = kk + ((lane & 8) ? 8 : 0);
                ldsm4(bh[nb], saB + (unsigned)(row * 40 + col) * 2);
                ldsm4(bl[nb], saB + (unsigned)(NTILE * 80) + (unsigned)(row * 40 + col) * 2);
            }
            #pragma unroll
            for (int mi = 0; mi < 2; mi++)
                #pragma unroll
                for (int nb = 0; nb < NI / 2; nb++) {
                    mma16816(acc[mi][2 * nb], ah[mi], &bh[nb][0]);
                    mma16816(acc[mi][2 * nb], ah[mi], &bl[nb][0]);
                    mma16816(acc[mi][2 * nb], al[mi], &bh[nb][0]);
                    mma16816(acc[mi][2 * nb + 1], ah[mi], &bh[nb][2]);
                    mma16816(acc[mi][2 * nb + 1], ah[mi], &bl[nb][2]);
                    mma16816(acc[mi][2 * nb + 1], al[mi], &bh[nb][2]);
                }
        }
    };

    loadB(0, 0);
    loadA(0);
    storeA(0);
    asm volatile("cp.async.wait_group 0;");
    __syncthreads();
    for (int c = 0; c < CH; c++) {
        int buf = c & 1;
        if (c + 1 < CH) { loadB(c + 1, buf ^ 1); loadA(c + 1); }
        compute(buf);
        if (c + 1 < CH) {
            storeA(buf ^ 1);
            asm volatile("cp.async.wait_group 0;");
        }
        __syncthreads();
    }
    #pragma unroll
    for (int mi = 0; mi < 2; mi++) {
        int grow0 = rowBase + wr * 32 + mi * 16 + (lane >> 2);
        int grow1 = grow0 + 8;
        #pragma unroll
        for (int ni = 0; ni < NI; ni++) {
            int gcol = colBase + wc * WN + ni * 8 + (lane & 3) * 2;
            float2 v0 = make_float2(acc[mi][ni][0], acc[mi][ni][1]);
            float2 v1 = make_float2(acc[mi][ni][2], acc[mi][ni][3]);
            if (JK) {
                float b0 = bias[gcol], b1 = bias[gcol + 1];
                v0.x += b0; v0.y += b1; v1.x += b0; v1.y += b1;
            }
            if (grow0 < M) *(float2*)(C + (size_t)grow0 * NT + gcol) = v0;
            if (grow1 < M) *(float2*)(C + (size_t)grow1 * NT + gcol) = v1;
        }
    }
    if (SCORES) {
        int head = (colBase >> 6) + wc;
        float as[NI][2], ad[NI][2];
        #pragma unroll
        for (int ni = 0; ni < NI; ni++) {
            int c = colBase + wc * WN + ni * 8 + (lane & 3) * 2;
            as[ni][0] = asrc[c]; as[ni][1] = asrc[c + 1];
            ad[ni][0] = adst[c]; ad[ni][1] = adst[c + 1];
        }
        #pragma unroll
        for (int mi = 0; mi < 2; mi++) {
            float e0 = 0.f, e1 = 0.f, d0 = 0.f, d1 = 0.f;
            #pragma unroll
            for (int ni = 0; ni < NI; ni++) {
                e0 = fmaf(acc[mi][ni][0], as[ni][0], e0);
                e0 = fmaf(acc[mi][ni][1], as[ni][1], e0);
                e1 = fmaf(acc[mi][ni][2], as[ni][0], e1);
                e1 = fmaf(acc[mi][ni][3], as[ni][1], e1);
                d0 = fmaf(acc[mi][ni][0], ad[ni][0], d0);
                d0 = fmaf(acc[mi][ni][1], ad[ni][1], d0);
                d1 = fmaf(acc[mi][ni][2], ad[ni][0], d1);
                d1 = fmaf(acc[mi][ni][3], ad[ni][1], d1);
            }
            e0 += __shfl_xor_sync(0xFFFFFFFFu, e0, 1); e0 += __shfl_xor_sync(0xFFFFFFFFu, e0, 2);
            e1 += __shfl_xor_sync(0xFFFFFFFFu, e1, 1); e1 += __shfl_xor_sync(0xFFFFFFFFu, e1, 2);
            d0 += __shfl_xor_sync(0xFFFFFFFFu, d0, 1); d0 += __shfl_xor_sync(0xFFFFFFFFu, d0, 2);
            d1 += __shfl_xor_sync(0xFFFFFFFFu, d1, 1); d1 += __shfl_xor_sync(0xFFFFFFFFu, d1, 2);
            if ((lane & 3) == 0) {
                int r0 = rowBase + wr * 32 + mi * 16 + (lane >> 2);
                int r1 = r0 + 8;
                if (r0 < M) { g_es[r0 * 4 + head] = e0; g_ed[r0 * 4 + head] = d0; }
                if (r1 < M) { g_es[r1 * 4 + head] = e1; g_ed[r1 * 4 + head] = d1; }
            }
        }
    }
}

// ---------------- fused softmax + aggregate (+BN stats): warp per node ----------------
template <int BN>
__global__ __launch_bounds__(256)
void softagg_k(const float* __restrict__ hfeat, const float* __restrict__ bias,
               float* __restrict__ out) {
    __shared__ float sal[8][32][4];
    int t = threadIdx.x, wid = t >> 5, lane = t & 31;
    int n = blockIdx.x * 8 + wid;
    int s = g_rowstart[n], en = g_rowstart[n + 1];
    int deg = en - s;
    bool small = (deg <= 32);
    int srcl = 0;

    if (deg > 0) {
        float4 ed = *(const float4*)&g_ed[n * 4];
        if (small) {
            float v0 = -1e30f, v1 = -1e30f, v2 = -1e30f, v3 = -1e30f;
            if (lane < deg) {
                srcl = g_csr_src[s + lane];
                float4 es = *(const float4*)&g_es[srcl * 4];
                v0 = es.x + ed.x; v0 = fmaxf(v0, 0.2f * v0);
                v1 = es.y + ed.y; v1 = fmaxf(v1, 0.2f * v1);
                v2 = es.z + ed.z; v2 = fmaxf(v2, 0.2f * v2);
                v3 = es.w + ed.w; v3 = fmaxf(v3, 0.2f * v3);
            }
            float m0 = v0, m1 = v1, m2 = v2, m3 = v3;
            #pragma unroll
            for (int o = 16; o > 0; o >>= 1) {
                m0 = fmaxf(m0, __shfl_xor_sync(0xFFFFFFFFu, m0, o));
                m1 = fmaxf(m1, __shfl_xor_sync(0xFFFFFFFFu, m1, o));
                m2 = fmaxf(m2, __shfl_xor_sync(0xFFFFFFFFu, m2, o));
                m3 = fmaxf(m3, __shfl_xor_sync(0xFFFFFFFFu, m3, o));
            }
            float p0 = 0.f, p1 = 0.f, p2 = 0.f, p3 = 0.f;
            if (lane < deg) {
                p0 = __expf(v0 - m0); p1 = __expf(v1 - m1);
                p2 = __expf(v2 - m2); p3 = __expf(v3 - m3);
            }
            float d0 = p0, d1 = p1, d2 = p2, d3 = p3;
            #pragma unroll
            for (int o = 16; o > 0; o >>= 1) {
                d0 += __shfl_xor_sync(0xFFFFFFFFu, d0, o);
                d1 += __shfl_xor_sync(0xFFFFFFFFu, d1, o);
                d2 += __shfl_xor_sync(0xFFFFFFFFu, d2, o);
                d3 += __shfl_xor_sync(0xFFFFFFFFu, d3, o);
            }
            if (lane < deg) {
                sal[wid][lane][0] = p0 / (d0 + 1e-16f);
                sal[wid][lane][1] = p1 / (d1 + 1e-16f);
                sal[wid][lane][2] = p2 / (d2 + 1e-16f);
                sal[wid][lane][3] = p3 / (d3 + 1e-16f);
            }
        } else {
            float m0 = -1e30f, m1 = -1e30f, m2 = -1e30f, m3 = -1e30f;
            for (int p = s + lane; p < en; p += 32) {
                int src = g_csr_src[p];
                float4 es = *(const float4*)&g_es[src * 4];
                float v0 = es.x + ed.x; v0 = fmaxf(v0, 0.2f * v0);
                float v1 = es.y + ed.y; v1 = fmaxf(v1, 0.2f * v1);
                float v2 = es.z + ed.z; v2 = fmaxf(v2, 0.2f * v2);
                float v3 = es.w + ed.w; v3 = fmaxf(v3, 0.2f * v3);
                m0 = fmaxf(m0, v0); m1 = fmaxf(m1, v1);
                m2 = fmaxf(m2, v2); m3 = fmaxf(m3, v3);
            }
            #pragma unroll
            for (int o = 16; o > 0; o >>= 1) {
                m0 = fmaxf(m0, __shfl_xor_sync(0xFFFFFFFFu, m0, o));
                m1 = fmaxf(m1, __shfl_xor_sync(0xFFFFFFFFu, m1, o));
                m2 = fmaxf(m2, __shfl_xor_sync(0xFFFFFFFFu, m2, o));
                m3 = fmaxf(m3, __shfl_xor_sync(0xFFFFFFFFu, m3, o));
            }
            float d0 = 0.f, d1 = 0.f, d2 = 0.f, d3 = 0.f;
            for (int p = s + lane; p < en; p += 32) {
                int src = g_csr_src[p];
                float4 es = *(const float4*)&g_es[src * 4];
                float v0 = es.x + ed.x; v0 = fmaxf(v0, 0.2f * v0);
                float v1 = es.y + ed.y; v1 = fmaxf(v1, 0.2f * v1);
                float v2 = es.z + ed.z; v2 = fmaxf(v2, 0.2f * v2);
                float v3 = es.w + ed.w; v3 = fmaxf(v3, 0.2f * v3);
                float4 a;
                a.x = __expf(v0 - m0); a.y = __expf(v1 - m1);
                a.z = __expf(v2 - m2); a.w = __expf(v3 - m3);
                d0 += a.x; d1 += a.y; d2 += a.z; d3 += a.w;
                *(float4*)&g_alpha[(size_t)p * 4] = a;
            }
            #pragma unroll
            for (int o = 16; o > 0; o >>= 1) {
                d0 += __shfl_xor_sync(0xFFFFFFFFu, d0, o);
                d1 += __shfl_xor_sync(0xFFFFFFFFu, d1, o);
                d2 += __shfl_xor_sync(0xFFFFFFFFu, d2, o);
                d3 += __shfl_xor_sync(0xFFFFFFFFu, d3, o);
            }
            float i0 = 1.f / (d0 + 1e-16f), i1 = 1.f / (d1 + 1e-16f);
            float i2 = 1.f / (d2 + 1e-16f), i3 = 1.f / (d3 + 1e-16f);
            for (int p = s + lane; p < en; p += 32) {
                float4 a = *(const float4*)&g_alpha[(size_t)p * 4];
                a.x *= i0; a.y *= i1; a.z *= i2; a.w *= i3;
                *(float4*)&g_alpha[(size_t)p * 4] = a;
            }
        }
    }
    __syncwarp();

    int h0 = lane >> 4, h1 = h0 + 2;
    int c0 = lane * 4, c1 = 128 + lane * 4;
    float4 A = {0, 0, 0, 0}, B = {0, 0, 0, 0};
    float4 A2 = {0, 0, 0, 0}, B2 = {0, 0, 0, 0};

    if (small) {
        int j = 0;
        for (; j + 4 <= deg; j += 4) {
            int s0 = __shfl_sync(0xFFFFFFFFu, srcl, j);
            int s1 = __shfl_sync(0xFFFFFFFFu, srcl, j + 1);
            int s2 = __shfl_sync(0xFFFFFFFFu, srcl, j + 2);
            int s3 = __shfl_sync(0xFFFFFFFFu, srcl, j + 3);
            float w0a = sal[wid][j][h0],     w0b = sal[wid][j][h1];
            float w1a = sal[wid][j + 1][h0], w1b = sal[wid][j + 1][h1];
            float w2a = sal[wid][j + 2][h0], w2b = sal[wid][j + 2][h1];
            float w3a = sal[wid][j + 3][h0], w3b = sal[wid][j + 3][h1];
            float4 f0a = *(const float4*)(hfeat + (size_t)s0 * HC + c0);
            float4 f0b = *(const float4*)(hfeat + (size_t)s0 * HC + c1);
            float4 f1a = *(const float4*)(hfeat + (size_t)s1 * HC + c0);
            float4 f1b = *(const float4*)(hfeat + (size_t)s1 * HC + c1);
            float4 f2a = *(const float4*)(hfeat + (size_t)s2 * HC + c0);
            float4 f2b = *(const float4*)(hfeat + (size_t)s2 * HC + c1);
            float4 f3a = *(const float4*)(hfeat + (size_t)s3 * HC + c0);
            float4 f3b = *(const float4*)(hfeat + (size_t)s3 * HC + c1);
            A.x = fmaf(w0a, f0a.x, A.x); A.y = fmaf(w0a, f0a.y, A.y);
            A.z = fmaf(w0a, f0a.z, A.z); A.w = fmaf(w0a, f0a.w, A.w);
            B.x = fmaf(w0b, f0b.x, B.x); B.y = fmaf(w0b, f0b.y, B.y);
            B.z = fmaf(w0b, f0b.z, B.z); B.w = fmaf(w0b, f0b.w, B.w);
            A2.x = fmaf(w1a, f1a.x, A2.x); A2.y = fmaf(w1a, f1a.y, A2.y);
            A2.z = fmaf(w1a, f1a.z, A2.z); A2.w = fmaf(w1a, f1a.w, A2.w);
            B2.x = fmaf(w1b, f1b.x, B2.x); B2.y = fmaf(w1b, f1b.y, B2.y);
            B2.z = fmaf(w1b, f1b.z, B2.z); B2.w = fmaf(w1b, f1b.w, B2.w);
            A.x = fmaf(w2a, f2a.x, A.x); A.y = fmaf(w2a, f2a.y, A.y);
            A.z = fmaf(w2a, f2a.z, A.z); A.w = fmaf(w2a, f2a.w, A.w);
            B.x = fmaf(w2b, f2b.x, B.x); B.y = fmaf(w2b, f2b.y, B.y);
            B.z = fmaf(w2b, f2b.z, B.z); B.w = fmaf(w2b, f2b.w, B.w);
            A2.x = fmaf(w3a, f3a.x, A2.x); A2.y = fmaf(w3a, f3a.y, A2.y);
            A2.z = fmaf(w3a, f3a.z, A2.z); A2.w = fmaf(w3a, f3a.w, A2.w);
            B2.x = fmaf(w3b, f3b.x, B2.x); B2.y = fmaf(w3b, f3b.y, B2.y);
            B2.z = fmaf(w3b, f3b.z, B2.z); B2.w = fmaf(w3b, f3b.w, B2.w);
        }
        for (; j < deg; j++) {
            int s0 = __shfl_sync(0xFFFFFFFFu, srcl, j);
            float wa = sal[wid][j][h0], wb = sal[wid][j][h1];
            float4 f0a = *(const float4*)(hfeat + (size_t)s0 * HC + c0);
            float4 f0b = *(const float4*)(hfeat + (size_t)s0 * HC + c1);
            A.x = fmaf(wa, f0a.x, A.x); A.y = fmaf(wa, f0a.y, A.y);
            A.z = fmaf(wa, f0a.z, A.z); A.w = fmaf(wa, f0a.w, A.w);
            B.x = fmaf(wb, f0b.x, B.x); B.y = fmaf(wb, f0b.y, B.y);
            B.z = fmaf(wb, f0b.z, B.z); B.w = fmaf(wb, f0b.w, B.w);
        }
    } else {
        int p = s;
        for (; p + 4 <= en; p += 4) {
            int s0 = g_csr_src[p], s1 = g_csr_src[p + 1];
            int s2 = g_csr_src[p + 2], s3 = g_csr_src[p + 3];
            float w0a = g_alpha[(size_t)p * 4 + h0],       w0b = g_alpha[(size_t)p * 4 + h1];
            float w1a = g_alpha[(size_t)(p + 1) * 4 + h0], w1b = g_alpha[(size_t)(p + 1) * 4 + h1];
            float w2a = g_alpha[(size_t)(p + 2) * 4 + h0], w2b = g_alpha[(size_t)(p + 2) * 4 + h1];
            float w3a = g_alpha[(size_t)(p + 3) * 4 + h0], w3b = g_alpha[(size_t)(p + 3) * 4 + h1];
            float4 f0a = *(const float4*)(hfeat + (size_t)s0 * HC + c0);
            float4 f0b = *(const float4*)(hfeat + (size_t)s0 * HC + c1);
            float4 f1a = *(const float4*)(hfeat + (size_t)s1 * HC + c0);
            float4 f1b = *(const float4*)(hfeat + (size_t)s1 * HC + c1);
            float4 f2a = *(const float4*)(hfeat + (size_t)s2 * HC + c0);
            float4 f2b = *(const float4*)(hfeat + (size_t)s2 * HC + c1);
            float4 f3a = *(const float4*)(hfeat + (size_t)s3 * HC + c0);
            float4 f3b = *(const float4*)(hfeat + (size_t)s3 * HC + c1);
            A.x = fmaf(w0a, f0a.x, A.x); A.y = fmaf(w0a, f0a.y, A.y);
            A.z = fmaf(w0a, f0a.z, A.z); A.w = fmaf(w0a, f0a.w, A.w);
            B.x = fmaf(w0b, f0b.x, B.x); B.y = fmaf(w0b, f0b.y, B.y);
            B.z = fmaf(w0b, f0b.z, B.z); B.w = fmaf(w0b, f0b.w, B.w);
            A2.x = fmaf(w1a, f1a.x, A2.x); A2.y = fmaf(w1a, f1a.y, A2.y);
            A2.z = fmaf(w1a, f1a.z, A2.z); A2.w = fmaf(w1a, f1a.w, A2.w);
            B2.x = fmaf(w1b, f1b.x, B2.x); B2.y = fmaf(w1b, f1b.y, B2.y);
            B2.z = fmaf(w1b, f1b.z, B2.z); B2.w = fmaf(w1b, f1b.w, B2.w);
            A.x = fmaf(w2a, f2a.x, A.x); A.y = fmaf(w2a, f2a.y, A.y);
            A.z = fmaf(w2a, f2a.z, A.z); A.w = fmaf(w2a, f2a.w, A.w);
            B.x = fmaf(w2b, f2b.x, B.x); B.y = fmaf(w2b, f2b.y, B.y);
            B.z = fmaf(w2b, f2b.z, B.z); B.w = fmaf(w2b, f2b.w, B.w);
            A2.x = fmaf(w3a, f3a.x, A2.x); A2.y = fmaf(w3a, f3a.y, A2.y);
            A2.z = fmaf(w3a, f3a.z, A2.z); A2.w = fmaf(w3a, f3a.w, A2.w);
            B2.x = fmaf(w3b, f3b.x, B2.x); B2.y = fmaf(w3b, f3b.y, B2.y);
            B2.z = fmaf(w3b, f3b.z, B2.z); B2.w = fmaf(w3b, f3b.w, B2.w);
        }
        for (; p < en; p++) {
            int s0 = g_csr_src[p];
            float wa = g_alpha[(size_t)p * 4 + h0], wb = g_alpha[(size_t)p * 4 + h1];
            float4 f0a = *(const float4*)(hfeat + (size_t)s0 * HC + c0);
            float4 f0b = *(const float4*)(hfeat + (size_t)s0 * HC + c1);
            A.x = fmaf(wa, f0a.x, A.x); A.y = fmaf(wa, f0a.y, A.y);
            A.z = fmaf(wa, f0a.z, A.z); A.w = fmaf(wa, f0a.w, A.w);
            B.x = fmaf(wb, f0b.x, B.x); B.y = fmaf(wb, f0b.y, B.y);
            B.z = fmaf(wb, f0b.z, B.z); B.w = fmaf(wb, f0b.w, B.w);
        }
    }
    float4 ba = *(const float4*)(bias + c0);
    float4 bb = *(const float4*)(bias + c1);
    float4 oa, ob;
    oa.x = A.x + A2.x + ba.x; oa.y = A.y + A2.y + ba.y;
    oa.z = A.z + A2.z + ba.z; oa.w = A.w + A2.w + ba.w;
    ob.x = B.x + B2.x + bb.x; ob.y = B.y + B2.y + bb.y;
    ob.z = B.z + B2.z + bb.z; ob.w = B.w + B2.w + bb.w;
    *(float4*)(out + (size_t)n * HC + c0) = oa;
    *(float4*)(out + (size_t)n * HC + c1) = ob;

    if (BN) {
        __syncthreads();
        sal[wid][lane][0] = oa.x; sal[wid][lane][1] = oa.y;
        sal[wid][lane][2] = oa.z; sal[wid][lane][3] = oa.w;
        __syncthreads();
        if (t < 128) {
            float sum = 0.f, sq = 0.f;
            #pragma unroll
            for (int w = 0; w < 8; w++) {
                float v = sal[w][t >> 2][t & 3];
                sum += v; sq += v * v;
            }
            atomicAdd(&g_bnsum[t], sum);
            atomicAdd(&g_bnsum[HC + t], sq);
        }
        __syncthreads();
        sal[wid][lane][0] = ob.x; sal[wid][lane][1] = ob.y;
        sal[wid][lane][2] = ob.z; sal[wid][lane][3] = ob.w;
        __syncthreads();
        if (t < 128) {
            float sum = 0.f, sq = 0.f;
            #pragma unroll
            for (int w = 0; w < 8; w++) {
                float v = sal[w][t >> 2][t & 3];
                sum += v; sq += v * v;
            }
            atomicAdd(&g_bnsum[128 + t], sum);
            atomicAdd(&g_bnsum[HC + 128 + t], sq);
        }
    }
}

// ---------------- BatchNorm apply (stats in g_bnsum) ----------------
__global__ __launch_bounds__(256)
void bn_apply_k(const float* __restrict__ x, const float* __restrict__ gamma,
                const float* __restrict__ beta, float* __restrict__ y) {
    __shared__ float ssc[HC], ssh[HC];
    int t = threadIdx.x;
    float mean = g_bnsum[t] / (float)NN;
    float var = g_bnsum[HC + t] / (float)NN - mean * mean;
    float sc = gamma[t] * rsqrtf(var + 1e-5f);
    ssc[t] = sc;
    ssh[t] = beta[t] - mean * sc;
    __syncthreads();
    for (long long i = blockIdx.x * 256 + t; i < (long long)NN * 64;
         i += (long long)gridDim.x * 256) {
        int ch = ((int)i & 63) * 4;
        float4 v = *(const float4*)(x + i * 4);
        v.x = v.x * ssc[ch] + ssh[ch];
        v.y = v.y * ssc[ch + 1] + ssh[ch + 1];
        v.z = v.z * ssc[ch + 2] + ssh[ch + 2];
        v.w = v.w * ssc[ch + 3] + ssh[ch + 3];
        v.x = (v.x > 0.f) ? v.x : expm1f(v.x);
        v.y = (v.y > 0.f) ? v.y : expm1f(v.y);
        v.z = (v.z > 0.f) ? v.z : expm1f(v.z);
        v.w = (v.w > 0.f) ? v.w : expm1f(v.w);
        *(float4*)(y + i * 4) = v;
    }
}

// ---------------- host ----------------
#define GDM ((NN + 127) / 128)
#define SMEM_128 (40960 + 2 * 128 * 160)   // 81920
#define SMEM_64  (40960 + 2 * 64 * 160)    // 61440

extern "C" void kernel_launch(void* const* d_in, const int* in_sizes, int n_in,
                              void* d_out, int out_size) {
    const float* x   = (const float*)d_in[0];
    const void*  eidx = d_in[1];
    const float* a1s = (const float*)d_in[3];
    const float* a1d = (const float*)d_in[4];
    const float* b1  = (const float*)d_in[5];
    const float* g1  = (const float*)d_in[6];
    const float* be1 = (const float*)d_in[7];
    const float* a2s = (const float*)d_in[9];
    const float* a2d = (const float*)d_in[10];
    const float* b2  = (const float*)d_in[11];
    const float* lb  = (const float*)d_in[13];
    float* out = (float*)d_out;

    float *ph, *pgat, *pl1, *pl2;
    cudaGetSymbolAddress((void**)&ph,   g_h);
    cudaGetSymbolAddress((void**)&pgat, g_gat);
    cudaGetSymbolAddress((void**)&pl1,  g_l1);
    cudaGetSymbolAddress((void**)&pl2,  g_l2);
    __nv_bfloat16 *w1h, *w1l, *w2h, *w2l, *w3h, *w3l;
    cudaGetSymbolAddress((void**)&w1h, g_w1t_hi);
    cudaGetSymbolAddress((void**)&w1l, g_w1t_lo);
    cudaGetSymbolAddress((void**)&w2h, g_w2t_hi);
    cudaGetSymbolAddress((void**)&w2l, g_w2t_lo);
    cudaGetSymbolAddress((void**)&w3h, g_w3t_hi);
    cudaGetSymbolAddress((void**)&w3l, g_w3t_lo);
    int* ppre;
    cudaGetSymbolAddress((void**)&ppre, g_pre);

    cudaFuncSetAttribute((const void*)mma_gemm_k<FIN, HC, 128, 2, 0, 1>,
                         cudaFuncAttributeMaxDynamicSharedMemorySize, SMEM_128);
    cudaFuncSetAttribute((const void*)mma_gemm_k<HC, HC, 128, 2, 0, 1>,
                         cudaFuncAttributeMaxDynamicSharedMemorySize, SMEM_128);
    cudaFuncSetAttribute((const void*)mma_gemm_k<HC, OUTC, 64, 2, 1, 0>,
                         cudaFuncAttributeMaxDynamicSharedMemorySize, SMEM_64);

    // fork-join: edge preprocessing + W2/W3 conversion run concurrently
    // with W1 conversion + gemm1 on the main stream
    cudaStream_t s2;
    cudaStreamCreateWithFlags(&s2, cudaStreamNonBlocking);
    cudaEvent_t evFork, evJoin;
    cudaEventCreateWithFlags(&evFork, cudaEventDisableTiming);
    cudaEventCreateWithFlags(&evJoin, cudaEventDisableTiming);

    cudaMemsetAsync(ppre, 0, (NN + 2 * SCB) * sizeof(int));
    cudaEventRecord(evFork, 0);
    cudaStreamWaitEvent(s2, evFork, 0);
    cvt_count_k<<<(EE + 255) / 256, 256, 0, s2>>>(eidx);
    scanfused_k<<<SCB, 256, 0, s2>>>();   // also zeroes g_bnsum
    fill_k<<<(EE + 255) / 256, 256, 0, s2>>>();
    wconv23_k<<<(HC * HC + HC * OUTC + 255) / 256, 256, 0, s2>>>(
        (const float*)d_in[8], (const float*)d_in[12]);
    cudaEventRecord(evJoin, s2);

    wconv1_k<<<(FIN * HC + 255) / 256, 256>>>((const float*)d_in[2]);
    {
        dim3 g(2, GDM);
        mma_gemm_k<FIN, HC, 128, 2, 0, 1><<<g, 256, SMEM_128>>>(
            x, nullptr, w1h, w1l, nullptr, ph, a1s, a1d, NN);
    }
    cudaStreamWaitEvent(0, evJoin, 0);

    softagg_k<1><<<NN / 8, 256>>>(ph, b1, pgat);
    bn_apply_k<<<592, 256>>>(pgat, g1, be1, pl1);

    {
        dim3 g(2, GDM);
        mma_gemm_k<HC, HC, 128, 2, 0, 1><<<g, 256, SMEM_128>>>(
            pl1, nullptr, w2h, w2l, nullptr, ph, a2s, a2d, NN);
    }
    softagg_k<0><<<NN / 8, 256>>>(ph, b2, pl2);

    {
        dim3 g(1, GDM);
        mma_gemm_k<HC, OUTC, 64, 2, 1, 0><<<g, 256, SMEM_64>>>(
            pl1, pl2, w3h, w3l, lb, out, nullptr, nullptr, NN);
    }
    // not destroying s2/events: destroying capture-participating objects
    // mid-capture is hazardous; kernel_launch is called O(1) times.
}

// round 15
// speedup vs baseline: 1.3896x; 1.3896x over previous
#include <cuda_runtime.h>
#include <cuda_bf16.h>
#include <math.h>

#define NN 40000
#define EE 320000
#define FIN 128
#define HH 4
#define HC 256
#define OUTC 64
#define SCB ((NN + 255) / 256)   // 157

// ---------------- scratch ----------------
__device__ int g_pre[NN + 2 * SCB];
__device__ __align__(16) int g_src[EE];
__device__ __align__(16) int g_dst[EE];
__device__ int g_rowstart[NN + 1];
__device__ int g_cursor[NN];
__device__ __align__(16) int g_csr_src[EE];
__device__ __align__(16) float g_h[(size_t)NN * HC];
__device__ __align__(16) float g_gat[(size_t)NN * HC];
__device__ __align__(16) float g_l1[(size_t)NN * HC];
__device__ __align__(16) float g_l2[(size_t)NN * HC];
__device__ __align__(16) float g_es[NN * HH];
__device__ __align__(16) float g_ed[NN * HH];
__device__ __align__(16) float g_alpha[(size_t)EE * HH];
__device__ float g_bnsum[2 * HC];
__device__ __align__(16) __nv_bfloat16 g_w1t_hi[HC * FIN];
__device__ __align__(16) __nv_bfloat16 g_w1t_lo[HC * FIN];
__device__ __align__(16) __nv_bfloat16 g_w2t_hi[HC * HC];
__device__ __align__(16) __nv_bfloat16 g_w2t_lo[HC * HC];
__device__ __align__(16) __nv_bfloat16 g_w3t_hi[OUTC * HC];
__device__ __align__(16) __nv_bfloat16 g_w3t_lo[OUTC * HC];

// ---------------- helpers ----------------
__device__ __forceinline__ unsigned smem_u32(const void* p) {
    unsigned r;
    asm("{ .reg .u64 t; cvta.to.shared.u64 t, %1; cvt.u32.u64 %0, t; }" : "=r"(r) : "l"(p));
    return r;
}
__device__ __forceinline__ unsigned pack2(float a, float b) {
    __nv_bfloat162 t = __floats2bfloat162_rn(a, b);
    return *reinterpret_cast<unsigned*>(&t);
}
__device__ __forceinline__ void ldsm4(unsigned* d, unsigned a) {
    asm volatile("ldmatrix.sync.aligned.m8n8.x4.shared.b16 {%0,%1,%2,%3}, [%4];"
                 : "=r"(d[0]), "=r"(d[1]), "=r"(d[2]), "=r"(d[3]) : "r"(a));
}
__device__ __forceinline__ void mma16816(float* c, const unsigned* a, const unsigned* b) {
    asm volatile(
        "mma.sync.aligned.m16n8k16.row.col.f32.bf16.bf16.f32 "
        "{%0,%1,%2,%3}, {%4,%5,%6,%7}, {%8,%9}, {%0,%1,%2,%3};"
        : "+f"(c[0]), "+f"(c[1]), "+f"(c[2]), "+f"(c[3])
        : "r"(a[0]), "r"(a[1]), "r"(a[2]), "r"(a[3]), "r"(b[0]), "r"(b[1]));
}
__device__ __forceinline__ void cp16(unsigned saddr, const void* gptr) {
    asm volatile("cp.async.cg.shared.global [%0], [%1], 16;" :: "r"(saddr), "l"(gptr));
}

// ---------------- preprocessing (detect merged into cvt) ----------------
__global__ void cvt_count_k(const void* __restrict__ idx) {
    __shared__ int is64s;
    if (threadIdx.x == 0) {
        const unsigned* buf = (const unsigned*)idx;
        int any = 0;
        #pragma unroll
        for (int i = 0; i < 64; i++) any |= (buf[2 * i + 1] != 0u);
        is64s = any ? 0 : 1;
    }
    __syncthreads();
    int e = blockIdx.x * blockDim.x + threadIdx.x;
    if (e >= EE) return;
    int s, d;
    if (is64s) {
        s = (int)((const long long*)idx)[e];
        d = (int)((const long long*)idx)[(long long)EE + e];
    } else {
        s = ((const int*)idx)[e];
        d = ((const int*)idx)[EE + e];
    }
    g_src[e] = s;
    g_dst[e] = d;
    atomicAdd(&g_pre[d], 1);
}
__global__ void scanfused_k() {
    int t = threadIdx.x, b = blockIdx.x;
    if (b == 0) { g_bnsum[t] = 0.f; g_bnsum[t + HC] = 0.f; }
    int i = b * 256 + t;
    int v = (i < NN) ? g_pre[i] : 0;
    int lane = t & 31, w = t >> 5;
    int x = v;
    #pragma unroll
    for (int d = 1; d < 32; d <<= 1) {
        int y = __shfl_up_sync(0xFFFFFFFFu, x, d);
        if (lane >= d) x += y;
    }
    __shared__ int ws[8];
    __shared__ int s_off;
    if (lane == 31) ws[w] = x;
    __syncthreads();
    if (t == 0) {
        int s = 0;
        #pragma unroll
        for (int j = 0; j < 8; j++) { s += ws[j]; ws[j] = s; }
        int total = s;
        int* part = g_pre + NN;
        int* pref = g_pre + NN + SCB;
        atomicExch(&part[b], total + 1);
        int run = 0;
        for (int j = b - 1; j >= 0;) {
            int pf = atomicAdd(&pref[j], 0);
            if (pf) { run += pf - 1; break; }
            int pt = atomicAdd(&part[j], 0);
            if (pt) { run += pt - 1; j--; }
        }
        atomicExch(&pref[b], run + total + 1);
        s_off = run;
    }
    __syncthreads();
    int incl = x + (w ? ws[w - 1] : 0);
    int off = s_off;
    if (i < NN) {
        int ex = off + incl - v;
        g_rowstart[i] = ex;
        g_cursor[i] = ex;
    }
    if (i == 0) g_rowstart[NN] = EE;
}
__global__ void fill_k() {
    int e = blockIdx.x * blockDim.x + threadIdx.x;
    if (e >= EE) return;
    int pos = atomicAdd(&g_cursor[g_dst[e]], 1);
    g_csr_src[pos] = g_src[e];
}

// ---------------- weight transpose + bf16 split (W1 alone; W2+W3 together) ----------------
__global__ void wconv1_k(const float* __restrict__ W1) {
    int idx = blockIdx.x * blockDim.x + threadIdx.x;
    if (idx >= FIN * HC) return;
    int k = idx / HC, n = idx % HC;
    float v = W1[idx];
    __nv_bfloat16 h = __float2bfloat16_rn(v);
    g_w1t_hi[(size_t)n * FIN + k] = h;
    g_w1t_lo[(size_t)n * FIN + k] = __float2bfloat16_rn(v - __bfloat162float(h));
}
__global__ void wconv23_k(const float* __restrict__ W2, const float* __restrict__ W3) {
    int gid = blockIdx.x * blockDim.x + threadIdx.x;
    const float* W;
    __nv_bfloat16 *Thi, *Tlo;
    int K, N, idx;
    if (gid < HC * HC) {
        W = W2; Thi = g_w2t_hi; Tlo = g_w2t_lo; K = HC; N = HC; idx = gid;
    } else if (gid < HC * HC + HC * OUTC) {
        W = W3; Thi = g_w3t_hi; Tlo = g_w3t_lo; K = HC; N = OUTC; idx = gid - HC * HC;
    } else return;
    int k = idx / N, n = idx % N;
    float v = W[idx];
    __nv_bfloat16 h = __float2bfloat16_rn(v);
    Thi[(size_t)n * K + k] = h;
    Tlo[(size_t)n * K + k] = __float2bfloat16_rn(v - __bfloat162float(h));
}

// ---------------- pipelined mma.sync split-bf16 GEMM (+ fused attention scores) ----------------
template <int KT, int NT, int NTILE, int WARPS_N, int JK, int SCORES>
__global__ __launch_bounds__(128 * WARPS_N, 2)
void mma_gemm_k(const float* __restrict__ A, const float* __restrict__ A2,
                const __nv_bfloat16* __restrict__ Bhi, const __nv_bfloat16* __restrict__ Blo,
                const float* __restrict__ bias, float* __restrict__ C,
                const float* __restrict__ asrc, const float* __restrict__ adst, int M) {
    constexpr int THREADS = 128 * WARPS_N;
    constexpr int WN = NTILE / WARPS_N;
    constexpr int NI = WN / 8;
    constexpr int LDA = 1024 / THREADS;
    constexpr int LDB = 8 * NTILE / THREADS;
    constexpr int CH = KT / 32;
    constexpr unsigned ABUF = 20480;
    constexpr unsigned BOFF = 2 * ABUF;
    constexpr unsigned BBUF = NTILE * 160;

    extern __shared__ char dynsm[];
    unsigned sbase = smem_u32(dynsm);
    int tid = threadIdx.x, lane = tid & 31, wid = tid >> 5;
    int wr = wid & 3, wc = wid >> 2;
    int rowBase = blockIdx.y * 128;
    int colBase = blockIdx.x * NTILE;
    float acc[2][NI][4] = {};
    float4 av[LDA], av2[LDA];

    auto loadA = [&](int c) {
        #pragma unroll
        for (int i = 0; i < LDA; i++) {
            int q = tid + i * THREADS;
            int r = q >> 3, cc = (q & 7) * 4;
            int grow = rowBase + r;
            av[i] = make_float4(0.f, 0.f, 0.f, 0.f);
            av2[i] = make_float4(0.f, 0.f, 0.f, 0.f);
            if (grow < M) {
                av[i] = *(const float4*)(A + (size_t)grow * KT + c * 32 + cc);
                if (JK) av2[i] = *(const float4*)(A2 + (size_t)grow * KT + c * 32 + cc);
            }
        }
    };
    auto storeA = [&](int buf) {
        #pragma unroll
        for (int i = 0; i < LDA; i++) {
            int q = tid + i * THREADS;
            int r = q >> 3, cc = (q & 7) * 4;
            float4 v = av[i];
            if (JK) {
                float4 w = av2[i];
                v.x = fmaxf(v.x, w.x); v.y = fmaxf(v.y, w.y);
                v.z = fmaxf(v.z, w.z); v.w = fmaxf(v.w, w.w);
            }
            float hx = __bfloat162float(__float2bfloat16_rn(v.x));
            float hy = __bfloat162float(__float2bfloat16_rn(v.y));
            float hz = __bfloat162float(__float2bfloat16_rn(v.z));
            float hw = __bfloat162float(__float2bfloat16_rn(v.w));
            unsigned off = buf * ABUF + (unsigned)(r * 40 + cc) * 2;
            *(uint2*)(dynsm + off) = make_uint2(pack2(hx, hy), pack2(hz, hw));
            *(uint2*)(dynsm + off + 10240) =
                make_uint2(pack2(v.x - hx, v.y - hy), pack2(v.z - hz, v.w - hw));
        }
    };
    auto loadB = [&](int c, int buf) {
        #pragma unroll
        for (int i = 0; i < LDB; i++) {
            int q = tid + i * THREADS;
            int hl = q / (4 * NTILE);
            int rem = q - hl * 4 * NTILE;
            int r = rem >> 2, seg = rem & 3;
            const __nv_bfloat16* src = hl ? Blo : Bhi;
            unsigned soff = BOFF + buf * BBUF + hl * (NTILE * 80) +
                            (unsigned)(r * 80 + seg * 16);
            cp16(sbase + soff, src + (size_t)(colBase + r) * KT + c * 32 + seg * 8);
        }
        asm volatile("cp.async.commit_group;");
    };
    auto compute = [&](int buf) {
        unsigned saA = sbase + buf * ABUF;
        unsigned saB = sbase + BOFF + buf * BBUF;
        #pragma unroll
        for (int kk = 0; kk < 32; kk += 16) {
            unsigned ah[2][4], al[2][4], bh[NI / 2][4], bl[NI / 2][4];
            #pragma unroll
            for (int mi = 0; mi < 2; mi++) {
                int row = wr * 32 + mi * 16 + (lane & 7) + ((lane & 8) ? 8 : 0);
                int col = kk + ((lane & 16) ? 8 : 0);
                ldsm4(ah[mi], saA + (unsigned)(row * 40 + col) * 2);
                ldsm4(al[mi], saA + 10240 + (unsigned)(row * 40 + col) * 2);
            }
            #pragma unroll
            for (int nb = 0; nb < NI / 2; nb++) {
                int row = wc * WN + nb * 16 + ((lane & 16) ? 8 : 0) + (lane & 7);
                int col = kk + ((lane & 8) ? 8 : 0);
                ldsm4(bh[nb], saB + (unsigned)(row * 40 + col) * 2);
                ldsm4(bl[nb], saB + (unsigned)(NTILE * 80) + (unsigned)(row * 40 + col) * 2);
            }
            #pragma unroll
            for (int mi = 0; mi < 2; mi++)
                #pragma unroll
                for (int nb = 0; nb < NI / 2; nb++) {
                    mma16816(acc[mi][2 * nb], ah[mi], &bh[nb][0]);
                    mma16816(acc[mi][2 * nb], ah[mi], &bl[nb][0]);
                    mma16816(acc[mi][2 * nb], al[mi], &bh[nb][0]);
                    mma16816(acc[mi][2 * nb + 1], ah[mi], &bh[nb][2]);
                    mma16816(acc[mi][2 * nb + 1], ah[mi], &bl[nb][2]);
                    mma16816(acc[mi][2 * nb + 1], al[mi], &bh[nb][2]);
                }
        }
    };

    loadB(0, 0);
    loadA(0);
    storeA(0);
    asm volatile("cp.async.wait_group 0;");
    __syncthreads();
    for (int c = 0; c < CH; c++) {
        int buf = c & 1;
        if (c + 1 < CH) { loadB(c + 1, buf ^ 1); loadA(c + 1); }
        compute(buf);
        if (c + 1 < CH) {
            storeA(buf ^ 1);
            asm volatile("cp.async.wait_group 0;");
        }
        __syncthreads();
    }
    #pragma unroll
    for (int mi = 0; mi < 2; mi++) {
        int grow0 = rowBase + wr * 32 + mi * 16 + (lane >> 2);
        int grow1 = grow0 + 8;
        #pragma unroll
        for (int ni = 0; ni < NI; ni++) {
            int gcol = colBase + wc * WN + ni * 8 + (lane & 3) * 2;
            float2 v0 = make_float2(acc[mi][ni][0], acc[mi][ni][1]);
            float2 v1 = make_float2(acc[mi][ni][2], acc[mi][ni][3]);
            if (JK) {
                float b0 = bias[gcol], b1 = bias[gcol + 1];
                v0.x += b0; v0.y += b1; v1.x += b0; v1.y += b1;
            }
            if (grow0 < M) *(float2*)(C + (size_t)grow0 * NT + gcol) = v0;
            if (grow1 < M) *(float2*)(C + (size_t)grow1 * NT + gcol) = v1;
        }
    }
    if (SCORES) {
        int head = (colBase >> 6) + wc;
        float as[NI][2], ad[NI][2];
        #pragma unroll
        for (int ni = 0; ni < NI; ni++) {
            int c = colBase + wc * WN + ni * 8 + (lane & 3) * 2;
            as[ni][0] = asrc[c]; as[ni][1] = asrc[c + 1];
            ad[ni][0] = adst[c]; ad[ni][1] = adst[c + 1];
        }
        #pragma unroll
        for (int mi = 0; mi < 2; mi++) {
            float e0 = 0.f, e1 = 0.f, d0 = 0.f, d1 = 0.f;
            #pragma unroll
            for (int ni = 0; ni < NI; ni++) {
                e0 = fmaf(acc[mi][ni][0], as[ni][0], e0);
                e0 = fmaf(acc[mi][ni][1], as[ni][1], e0);
                e1 = fmaf(acc[mi][ni][2], as[ni][0], e1);
                e1 = fmaf(acc[mi][ni][3], as[ni][1], e1);
                d0 = fmaf(acc[mi][ni][0], ad[ni][0], d0);
                d0 = fmaf(acc[mi][ni][1], ad[ni][1], d0);
                d1 = fmaf(acc[mi][ni][2], ad[ni][0], d1);
                d1 = fmaf(acc[mi][ni][3], ad[ni][1], d1);
            }
            e0 += __shfl_xor_sync(0xFFFFFFFFu, e0, 1); e0 += __shfl_xor_sync(0xFFFFFFFFu, e0, 2);
            e1 += __shfl_xor_sync(0xFFFFFFFFu, e1, 1); e1 += __shfl_xor_sync(0xFFFFFFFFu, e1, 2);
            d0 += __shfl_xor_sync(0xFFFFFFFFu, d0, 1); d0 += __shfl_xor_sync(0xFFFFFFFFu, d0, 2);
            d1 += __shfl_xor_sync(0xFFFFFFFFu, d1, 1); d1 += __shfl_xor_sync(0xFFFFFFFFu, d1, 2);
            if ((lane & 3) == 0) {
                int r0 = rowBase + wr * 32 + mi * 16 + (lane >> 2);
                int r1 = r0 + 8;
                if (r0 < M) { g_es[r0 * 4 + head] = e0; g_ed[r0 * 4 + head] = d0; }
                if (r1 < M) { g_es[r1 * 4 + head] = e1; g_ed[r1 * 4 + head] = d1; }
            }
        }
    }
}

// ---------------- fused softmax + aggregate (+BN stats): warp per node ----------------
template <int BN>
__global__ __launch_bounds__(256)
void softagg_k(const float* __restrict__ hfeat, const float* __restrict__ bias,
               float* __restrict__ out) {
    __shared__ float sal[8][32][4];
    int t = threadIdx.x, wid = t >> 5, lane = t & 31;
    int n = blockIdx.x * 8 + wid;
    int s = g_rowstart[n], en = g_rowstart[n + 1];
    int deg = en - s;
    bool small = (deg <= 32);
    int srcl = 0;

    if (deg > 0) {
        float4 ed = *(const float4*)&g_ed[n * 4];
        if (small) {
            float v0 = -1e30f, v1 = -1e30f, v2 = -1e30f, v3 = -1e30f;
            if (lane < deg) {
                srcl = g_csr_src[s + lane];
                float4 es = *(const float4*)&g_es[srcl * 4];
                v0 = es.x + ed.x; v0 = fmaxf(v0, 0.2f * v0);
                v1 = es.y + ed.y; v1 = fmaxf(v1, 0.2f * v1);
                v2 = es.z + ed.z; v2 = fmaxf(v2, 0.2f * v2);
                v3 = es.w + ed.w; v3 = fmaxf(v3, 0.2f * v3);
            }
            float m0 = v0, m1 = v1, m2 = v2, m3 = v3;
            #pragma unroll
            for (int o = 16; o > 0; o >>= 1) {
                m0 = fmaxf(m0, __shfl_xor_sync(0xFFFFFFFFu, m0, o));
                m1 = fmaxf(m1, __shfl_xor_sync(0xFFFFFFFFu, m1, o));
                m2 = fmaxf(m2, __shfl_xor_sync(0xFFFFFFFFu, m2, o));
                m3 = fmaxf(m3, __shfl_xor_sync(0xFFFFFFFFu, m3, o));
            }
            float p0 = 0.f, p1 = 0.f, p2 = 0.f, p3 = 0.f;
            if (lane < deg) {
                p0 = __expf(v0 - m0); p1 = __expf(v1 - m1);
                p2 = __expf(v2 - m2); p3 = __expf(v3 - m3);
            }
            float d0 = p0, d1 = p1, d2 = p2, d3 = p3;
            #pragma unroll
            for (int o = 16; o > 0; o >>= 1) {
                d0 += __shfl_xor_sync(0xFFFFFFFFu, d0, o);
                d1 += __shfl_xor_sync(0xFFFFFFFFu, d1, o);
                d2 += __shfl_xor_sync(0xFFFFFFFFu, d2, o);
                d3 += __shfl_xor_sync(0xFFFFFFFFu, d3, o);
            }
            if (lane < deg) {
                sal[wid][lane][0] = p0 / (d0 + 1e-16f);
                sal[wid][lane][1] = p1 / (d1 + 1e-16f);
                sal[wid][lane][2] = p2 / (d2 + 1e-16f);
                sal[wid][lane][3] = p3 / (d3 + 1e-16f);
            }
        } else {
            float m0 = -1e30f, m1 = -1e30f, m2 = -1e30f, m3 = -1e30f;
            for (int p = s + lane; p < en; p += 32) {
                int src = g_csr_src[p];
                float4 es = *(const float4*)&g_es[src * 4];
                float v0 = es.x + ed.x; v0 = fmaxf(v0, 0.2f * v0);
                float v1 = es.y + ed.y; v1 = fmaxf(v1, 0.2f * v1);
                float v2 = es.z + ed.z; v2 = fmaxf(v2, 0.2f * v2);
                float v3 = es.w + ed.w; v3 = fmaxf(v3, 0.2f * v3);
                m0 = fmaxf(m0, v0); m1 = fmaxf(m1, v1);
                m2 = fmaxf(m2, v2); m3 = fmaxf(m3, v3);
            }
            #pragma unroll
            for (int o = 16; o > 0; o >>= 1) {
                m0 = fmaxf(m0, __shfl_xor_sync(0xFFFFFFFFu, m0, o));
                m1 = fmaxf(m1, __shfl_xor_sync(0xFFFFFFFFu, m1, o));
                m2 = fmaxf(m2, __shfl_xor_sync(0xFFFFFFFFu, m2, o));
                m3 = fmaxf(m3, __shfl_xor_sync(0xFFFFFFFFu, m3, o));
            }
            float d0 = 0.f, d1 = 0.f, d2 = 0.f, d3 = 0.f;
            for (int p = s + lane; p < en; p += 32) {
                int src = g_csr_src[p];
                float4 es = *(const float4*)&g_es[src * 4];
                float v0 = es.x + ed.x; v0 = fmaxf(v0, 0.2f * v0);
                float v1 = es.y + ed.y; v1 = fmaxf(v1, 0.2f * v1);
                float v2 = es.z + ed.z; v2 = fmaxf(v2, 0.2f * v2);
                float v3 = es.w + ed.w; v3 = fmaxf(v3, 0.2f * v3);
                float4 a;
                a.x = __expf(v0 - m0); a.y = __expf(v1 - m1);
                a.z = __expf(v2 - m2); a.w = __expf(v3 - m3);
                d0 += a.x; d1 += a.y; d2 += a.z; d3 += a.w;
                *(float4*)&g_alpha[(size_t)p * 4] = a;
            }
            #pragma unroll
            for (int o = 16; o > 0; o >>= 1) {
                d0 += __shfl_xor_sync(0xFFFFFFFFu, d0, o);
                d1 += __shfl_xor_sync(0xFFFFFFFFu, d1, o);
                d2 += __shfl_xor_sync(0xFFFFFFFFu, d2, o);
                d3 += __shfl_xor_sync(0xFFFFFFFFu, d3, o);
            }
            float i0 = 1.f / (d0 + 1e-16f), i1 = 1.f / (d1 + 1e-16f);
            float i2 = 1.f / (d2 + 1e-16f), i3 = 1.f / (d3 + 1e-16f);
            for (int p = s + lane; p < en; p += 32) {
                float4 a = *(const float4*)&g_alpha[(size_t)p * 4];
                a.x *= i0; a.y *= i1; a.z *= i2; a.w *= i3;
                *(float4*)&g_alpha[(size_t)p * 4] = a;
            }
        }
    }
    __syncwarp();

    int h0 = lane >> 4, h1 = h0 + 2;
    int c0 = lane * 4, c1 = 128 + lane * 4;
    float4 A = {0, 0, 0, 0}, B = {0, 0, 0, 0};
    float4 A2 = {0, 0, 0, 0}, B2 = {0, 0, 0, 0};

    if (small) {
        int j = 0;
        for (; j + 4 <= deg; j += 4) {
            int s0 = __shfl_sync(0xFFFFFFFFu, srcl, j);
            int s1 = __shfl_sync(0xFFFFFFFFu, srcl, j + 1);
            int s2 = __shfl_sync(0xFFFFFFFFu, srcl, j + 2);
            int s3 = __shfl_sync(0xFFFFFFFFu, srcl, j + 3);
            float w0a = sal[wid][j][h0],     w0b = sal[wid][j][h1];
            float w1a = sal[wid][j + 1][h0], w1b = sal[wid][j + 1][h1];
            float w2a = sal[wid][j + 2][h0], w2b = sal[wid][j + 2][h1];
            float w3a = sal[wid][j + 3][h0], w3b = sal[wid][j + 3][h1];
            float4 f0a = *(const float4*)(hfeat + (size_t)s0 * HC + c0);
            float4 f0b = *(const float4*)(hfeat + (size_t)s0 * HC + c1);
            float4 f1a = *(const float4*)(hfeat + (size_t)s1 * HC + c0);
            float4 f1b = *(const float4*)(hfeat + (size_t)s1 * HC + c1);
            float4 f2a = *(const float4*)(hfeat + (size_t)s2 * HC + c0);
            float4 f2b = *(const float4*)(hfeat + (size_t)s2 * HC + c1);
            float4 f3a = *(const float4*)(hfeat + (size_t)s3 * HC + c0);
            float4 f3b = *(const float4*)(hfeat + (size_t)s3 * HC + c1);
            A.x = fmaf(w0a, f0a.x, A.x); A.y = fmaf(w0a, f0a.y, A.y);
            A.z = fmaf(w0a, f0a.z, A.z); A.w = fmaf(w0a, f0a.w, A.w);
            B.x = fmaf(w0b, f0b.x, B.x); B.y = fmaf(w0b, f0b.y, B.y);
            B.z = fmaf(w0b, f0b.z, B.z); B.w = fmaf(w0b, f0b.w, B.w);
            A2.x = fmaf(w1a, f1a.x, A2.x); A2.y = fmaf(w1a, f1a.y, A2.y);
            A2.z = fmaf(w1a, f1a.z, A2.z); A2.w = fmaf(w1a, f1a.w, A2.w);
            B2.x = fmaf(w1b, f1b.x, B2.x); B2.y = fmaf(w1b, f1b.y, B2.y);
            B2.z = fmaf(w1b, f1b.z, B2.z); B2.w = fmaf(w1b, f1b.w, B2.w);
            A.x = fmaf(w2a, f2a.x, A.x); A.y = fmaf(w2a, f2a.y, A.y);
            A.z = fmaf(w2a, f2a.z, A.z); A.w = fmaf(w2a, f2a.w, A.w);
            B.x = fmaf(w2b, f2b.x, B.x); B.y = fmaf(w2b, f2b.y, B.y);
            B.z = fmaf(w2b, f2b.z, B.z); B.w = fmaf(w2b, f2b.w, B.w);
            A2.x = fmaf(w3a, f3a.x, A2.x); A2.y = fmaf(w3a, f3a.y, A2.y);
            A2.z = fmaf(w3a, f3a.z, A2.z); A2.w = fmaf(w3a, f3a.w, A2.w);
            B2.x = fmaf(w3b, f3b.x, B2.x); B2.y = fmaf(w3b, f3b.y, B2.y);
            B2.z = fmaf(w3b, f3b.z, B2.z); B2.w = fmaf(w3b, f3b.w, B2.w);
        }
        for (; j < deg; j++) {
            int s0 = __shfl_sync(0xFFFFFFFFu, srcl, j);
            float wa = sal[wid][j][h0], wb = sal[wid][j][h1];
            float4 f0a = *(const float4*)(hfeat + (size_t)s0 * HC + c0);
            float4 f0b = *(const float4*)(hfeat + (size_t)s0 * HC + c1);
            A.x = fmaf(wa, f0a.x, A.x); A.y = fmaf(wa, f0a.y, A.y);
            A.z = fmaf(wa, f0a.z, A.z); A.w = fmaf(wa, f0a.w, A.w);
            B.x = fmaf(wb, f0b.x, B.x); B.y = fmaf(wb, f0b.y, B.y);
            B.z = fmaf(wb, f0b.z, B.z); B.w = fmaf(wb, f0b.w, B.w);
        }
    } else {
        int p = s;
        for (; p + 4 <= en; p += 4) {
            int s0 = g_csr_src[p], s1 = g_csr_src[p + 1];
            int s2 = g_csr_src[p + 2], s3 = g_csr_src[p + 3];
            float w0a = g_alpha[(size_t)p * 4 + h0],       w0b = g_alpha[(size_t)p * 4 + h1];
            float w1a = g_alpha[(size_t)(p + 1) * 4 + h0], w1b = g_alpha[(size_t)(p + 1) * 4 + h1];
            float w2a = g_alpha[(size_t)(p + 2) * 4 + h0], w2b = g_alpha[(size_t)(p + 2) * 4 + h1];
            float w3a = g_alpha[(size_t)(p + 3) * 4 + h0], w3b = g_alpha[(size_t)(p + 3) * 4 + h1];
            float4 f0a = *(const float4*)(hfeat + (size_t)s0 * HC + c0);
            float4 f0b = *(const float4*)(hfeat + (size_t)s0 * HC + c1);
            float4 f1a = *(const float4*)(hfeat + (size_t)s1 * HC + c0);
            float4 f1b = *(const float4*)(hfeat + (size_t)s1 * HC + c1);
            float4 f2a = *(const float4*)(hfeat + (size_t)s2 * HC + c0);
            float4 f2b = *(const float4*)(hfeat + (size_t)s2 * HC + c1);
            float4 f3a = *(const float4*)(hfeat + (size_t)s3 * HC + c0);
            float4 f3b = *(const float4*)(hfeat + (size_t)s3 * HC + c1);
            A.x = fmaf(w0a, f0a.x, A.x); A.y = fmaf(w0a, f0a.y, A.y);
            A.z = fmaf(w0a, f0a.z, A.z); A.w = fmaf(w0a, f0a.w, A.w);
            B.x = fmaf(w0b, f0b.x, B.x); B.y = fmaf(w0b, f0b.y, B.y);
            B.z = fmaf(w0b, f0b.z, B.z); B.w = fmaf(w0b, f0b.w, B.w);
            A2.x = fmaf(w1a, f1a.x, A2.x); A2.y = fmaf(w1a, f1a.y, A2.y);
            A2.z = fmaf(w1a, f1a.z, A2.z); A2.w = fmaf(w1a, f1a.w, A2.w);
            B2.x = fmaf(w1b, f1b.x, B2.x); B2.y = fmaf(w1b, f1b.y, B2.y);
            B2.z = fmaf(w1b, f1b.z, B2.z); B2.w = fmaf(w1b, f1b.w, B2.w);
            A.x = fmaf(w2a, f2a.x, A.x); A.y = fmaf(w2a, f2a.y, A.y);
            A.z = fmaf(w2a, f2a.z, A.z); A.w = fmaf(w2a, f2a.w, A.w);
            B.x = fmaf(w2b, f2b.x, B.x); B.y = fmaf(w2b, f2b.y, B.y);
            B.z = fmaf(w2b, f2b.z, B.z); B.w = fmaf(w2b, f2b.w, B.w);
            A2.x = fmaf(w3a, f3a.x, A2.x); A2.y = fmaf(w3a, f3a.y, A2.y);
            A2.z = fmaf(w3a, f3a.z, A2.z); A2.w = fmaf(w3a, f3a.w, A2.w);
            B2.x = fmaf(w3b, f3b.x, B2.x); B2.y = fmaf(w3b, f3b.y, B2.y);
            B2.z = fmaf(w3b, f3b.z, B2.z); B2.w = fmaf(w3b, f3b.w, B2.w);
        }
        for (; p < en; p++) {
            int s0 = g_csr_src[p];
            float wa = g_alpha[(size_t)p * 4 + h0], wb = g_alpha[(size_t)p * 4 + h1];
            float4 f0a = *(const float4*)(hfeat + (size_t)s0 * HC + c0);
            float4 f0b = *(const float4*)(hfeat + (size_t)s0 * HC + c1);
            A.x = fmaf(wa, f0a.x, A.x); A.y = fmaf(wa, f0a.y, A.y);
            A.z = fmaf(wa, f0a.z, A.z); A.w = fmaf(wa, f0a.w, A.w);
            B.x = fmaf(wb, f0b.x, B.x); B.y = fmaf(wb, f0b.y, B.y);
            B.z = fmaf(wb, f0b.z, B.z); B.w = fmaf(wb, f0b.w, B.w);
        }
    }
    float4 ba = *(const float4*)(bias + c0);
    float4 bb = *(const float4*)(bias + c1);
    float4 oa, ob;
    oa.x = A.x + A2.x + ba.x; oa.y = A.y + A2.y + ba.y;
    oa.z = A.z + A2.z + ba.z; oa.w = A.w + A2.w + ba.w;
    ob.x = B.x + B2.x + bb.x; ob.y = B.y + B2.y + bb.y;
    ob.z = B.z + B2.z + bb.z; ob.w = B.w + B2.w + bb.w;
    *(float4*)(out + (size_t)n * HC + c0) = oa;
    *(float4*)(out + (size_t)n * HC + c1) = ob;

    if (BN) {
        __syncthreads();
        sal[wid][lane][0] = oa.x; sal[wid][lane][1] = oa.y;
        sal[wid][lane][2] = oa.z; sal[wid][lane][3] = oa.w;
        __syncthreads();
        if (t < 128) {
            float sum = 0.f, sq = 0.f;
            #pragma unroll
            for (int w = 0; w < 8; w++) {
                float v = sal[w][t >> 2][t & 3];
                sum += v; sq += v * v;
            }
            atomicAdd(&g_bnsum[t], sum);
            atomicAdd(&g_bnsum[HC + t], sq);
        }
        __syncthreads();
        sal[wid][lane][0] = ob.x; sal[wid][lane][1] = ob.y;
        sal[wid][lane][2] = ob.z; sal[wid][lane][3] = ob.w;
        __syncthreads();
        if (t < 128) {
            float sum = 0.f, sq = 0.f;
            #pragma unroll
            for (int w = 0; w < 8; w++) {
                float v = sal[w][t >> 2][t & 3];
                sum += v; sq += v * v;
            }
            atomicAdd(&g_bnsum[128 + t], sum);
            atomicAdd(&g_bnsum[HC + 128 + t], sq);
        }
    }
}

// ---------------- BatchNorm apply (stats in g_bnsum) ----------------
__global__ __launch_bounds__(256)
void bn_apply_k(const float* __restrict__ x, const float* __restrict__ gamma,
                const float* __restrict__ beta, float* __restrict__ y) {
    __shared__ float ssc[HC], ssh[HC];
    int t = threadIdx.x;
    float mean = g_bnsum[t] / (float)NN;
    float var = g_bnsum[HC + t] / (float)NN - mean * mean;
    float sc = gamma[t] * rsqrtf(var + 1e-5f);
    ssc[t] = sc;
    ssh[t] = beta[t] - mean * sc;
    __syncthreads();
    for (long long i = blockIdx.x * 256 + t; i < (long long)NN * 64;
         i += (long long)gridDim.x * 256) {
        int ch = ((int)i & 63) * 4;
        float4 v = *(const float4*)(x + i * 4);
        v.x = v.x * ssc[ch] + ssh[ch];
        v.y = v.y * ssc[ch + 1] + ssh[ch + 1];
        v.z = v.z * ssc[ch + 2] + ssh[ch + 2];
        v.w = v.w * ssc[ch + 3] + ssh[ch + 3];
        v.x = (v.x > 0.f) ? v.x : expm1f(v.x);
        v.y = (v.y > 0.f) ? v.y : expm1f(v.y);
        v.z = (v.z > 0.f) ? v.z : expm1f(v.z);
        v.w = (v.w > 0.f) ? v.w : expm1f(v.w);
        *(float4*)(y + i * 4) = v;
    }
}

// ---------------- host ----------------
#define GDM ((NN + 127) / 128)
#define SMEM_128 (40960 + 2 * 128 * 160)   // 81920
#define SMEM_64  (40960 + 2 * 64 * 160)    // 61440

extern "C" void kernel_launch(void* const* d_in, const int* in_sizes, int n_in,
                              void* d_out, int out_size) {
    const float* x   = (const float*)d_in[0];
    const void*  eidx = d_in[1];
    const float* a1s = (const float*)d_in[3];
    const float* a1d = (const float*)d_in[4];
    const float* b1  = (const float*)d_in[5];
    const float* g1  = (const float*)d_in[6];
    const float* be1 = (const float*)d_in[7];
    const float* a2s = (const float*)d_in[9];
    const float* a2d = (const float*)d_in[10];
    const float* b2  = (const float*)d_in[11];
    const float* lb  = (const float*)d_in[13];
    float* out = (float*)d_out;

    float *ph, *pgat, *pl1, *pl2;
    cudaGetSymbolAddress((void**)&ph,   g_h);
    cudaGetSymbolAddress((void**)&pgat, g_gat);
    cudaGetSymbolAddress((void**)&pl1,  g_l1);
    cudaGetSymbolAddress((void**)&pl2,  g_l2);
    __nv_bfloat16 *w1h, *w1l, *w2h, *w2l, *w3h, *w3l;
    cudaGetSymbolAddress((void**)&w1h, g_w1t_hi);
    cudaGetSymbolAddress((void**)&w1l, g_w1t_lo);
    cudaGetSymbolAddress((void**)&w2h, g_w2t_hi);
    cudaGetSymbolAddress((void**)&w2l, g_w2t_lo);
    cudaGetSymbolAddress((void**)&w3h, g_w3t_hi);
    cudaGetSymbolAddress((void**)&w3l, g_w3t_lo);
    int* ppre;
    cudaGetSymbolAddress((void**)&ppre, g_pre);

    cudaFuncSetAttribute((const void*)mma_gemm_k<FIN, HC, 128, 2, 0, 1>,
                         cudaFuncAttributeMaxDynamicSharedMemorySize, SMEM_128);
    cudaFuncSetAttribute((const void*)mma_gemm_k<HC, HC, 128, 2, 0, 1>,
                         cudaFuncAttributeMaxDynamicSharedMemorySize, SMEM_128);
    cudaFuncSetAttribute((const void*)mma_gemm_k<HC, OUTC, 64, 2, 1, 0>,
                         cudaFuncAttributeMaxDynamicSharedMemorySize, SMEM_64);

    // fork-join: edge preprocessing + W2/W3 conversion run concurrently
    // with W1 conversion + gemm1 on the main stream
    cudaStream_t s2;
    cudaStreamCreateWithFlags(&s2, cudaStreamNonBlocking);
    cudaEvent_t evFork, evJoin;
    cudaEventCreateWithFlags(&evFork, cudaEventDisableTiming);
    cudaEventCreateWithFlags(&evJoin, cudaEventDisableTiming);

    cudaMemsetAsync(ppre, 0, (NN + 2 * SCB) * sizeof(int));
    cudaEventRecord(evFork, 0);
    cudaStreamWaitEvent(s2, evFork, 0);
    cvt_count_k<<<(EE + 255) / 256, 256, 0, s2>>>(eidx);
    scanfused_k<<<SCB, 256, 0, s2>>>();   // also zeroes g_bnsum
    fill_k<<<(EE + 255) / 256, 256, 0, s2>>>();
    wconv23_k<<<(HC * HC + HC * OUTC + 255) / 256, 256, 0, s2>>>(
        (const float*)d_in[8], (const float*)d_in[12]);
    cudaEventRecord(evJoin, s2);

    wconv1_k<<<(FIN * HC + 255) / 256, 256>>>((const float*)d_in[2]);
    {
        dim3 g(2, GDM);
        mma_gemm_k<FIN, HC, 128, 2, 0, 1><<<g, 256, SMEM_128>>>(
            x, nullptr, w1h, w1l, nullptr, ph, a1s, a1d, NN);
    }
    cudaStreamWaitEvent(0, evJoin, 0);

    softagg_k<1><<<NN / 8, 256>>>(ph, b1, pgat);
    bn_apply_k<<<592, 256>>>(pgat, g1, be1, pl1);

    {
        dim3 g(2, GDM);
        mma_gemm_k<HC, HC, 128, 2, 0, 1><<<g, 256, SMEM_128>>>(
            pl1, nullptr, w2h, w2l, nullptr, ph, a2s, a2d, NN);
    }
    softagg_k<0><<<NN / 8, 256>>>(ph, b2, pl2);

    {
        dim3 g(1, GDM);
        mma_gemm_k<HC, OUTC, 64, 2, 1, 0><<<g, 256, SMEM_64>>>(
            pl1, pl2, w3h, w3l, lb, out, nullptr, nullptr, NN);
    }
    // not destroying s2/events: destroying capture-participating objects
    // mid-capture is hazardous; kernel_launch is called O(1) times.
}

// round 16
// speedup vs baseline: 1.3928x; 1.0023x over previous
#include <cuda_runtime.h>
#include <cuda_bf16.h>
#include <math.h>

#define NN 40000
#define EE 320000
#define FIN 128
#define HH 4
#define HC 256
#define OUTC 64
#define SCB ((NN + 255) / 256)   // 157

// ---------------- scratch ----------------
__device__ int g_pre[NN + 2 * SCB];
__device__ __align__(16) int g_src[EE];
__device__ __align__(16) int g_dst[EE];
__device__ int g_rowstart[NN + 1];
__device__ int g_cursor[NN];
__device__ __align__(16) int g_csr_src[EE];
__device__ __align__(16) float g_h[(size_t)NN * HC];
__device__ __align__(16) float g_gat[(size_t)NN * HC];
__device__ __align__(16) float g_l1[(size_t)NN * HC];
__device__ __align__(16) float g_l2[(size_t)NN * HC];
__device__ __align__(16) float g_es[NN * HH];
__device__ __align__(16) float g_ed[NN * HH];
__device__ __align__(16) float g_alpha[(size_t)EE * HH];
__device__ float g_bnsum[2 * HC];
__device__ __align__(16) __nv_bfloat16 g_w1t_hi[HC * FIN];
__device__ __align__(16) __nv_bfloat16 g_w1t_lo[HC * FIN];
__device__ __align__(16) __nv_bfloat16 g_w2t_hi[HC * HC];
__device__ __align__(16) __nv_bfloat16 g_w2t_lo[HC * HC];
__device__ __align__(16) __nv_bfloat16 g_w3t_hi[OUTC * HC];
__device__ __align__(16) __nv_bfloat16 g_w3t_lo[OUTC * HC];

// ---------------- helpers ----------------
__device__ __forceinline__ unsigned smem_u32(const void* p) {
    unsigned r;
    asm("{ .reg .u64 t; cvta.to.shared.u64 t, %1; cvt.u32.u64 %0, t; }" : "=r"(r) : "l"(p));
    return r;
}
__device__ __forceinline__ unsigned pack2(float a, float b) {
    __nv_bfloat162 t = __floats2bfloat162_rn(a, b);
    return *reinterpret_cast<unsigned*>(&t);
}
__device__ __forceinline__ void ldsm4(unsigned* d, unsigned a) {
    asm volatile("ldmatrix.sync.aligned.m8n8.x4.shared.b16 {%0,%1,%2,%3}, [%4];"
                 : "=r"(d[0]), "=r"(d[1]), "=r"(d[2]), "=r"(d[3]) : "r"(a));
}
__device__ __forceinline__ void mma16816(float* c, const unsigned* a, const unsigned* b) {
    asm volatile(
        "mma.sync.aligned.m16n8k16.row.col.f32.bf16.bf16.f32 "
        "{%0,%1,%2,%3}, {%4,%5,%6,%7}, {%8,%9}, {%0,%1,%2,%3};"
        : "+f"(c[0]), "+f"(c[1]), "+f"(c[2]), "+f"(c[3])
        : "r"(a[0]), "r"(a[1]), "r"(a[2]), "r"(a[3]), "r"(b[0]), "r"(b[1]));
}
__device__ __forceinline__ void cp16(unsigned saddr, const void* gptr) {
    asm volatile("cp.async.cg.shared.global [%0], [%1], 16;" :: "r"(saddr), "l"(gptr));
}

// ---------------- preprocessing (detect merged into cvt) ----------------
__global__ void cvt_count_k(const void* __restrict__ idx) {
    __shared__ int is64s;
    if (threadIdx.x == 0) {
        const unsigned* buf = (const unsigned*)idx;
        int any = 0;
        #pragma unroll
        for (int i = 0; i < 64; i++) any |= (buf[2 * i + 1] != 0u);
        is64s = any ? 0 : 1;
    }
    __syncthreads();
    int e = blockIdx.x * blockDim.x + threadIdx.x;
    if (e >= EE) return;
    int s, d;
    if (is64s) {
        s = (int)((const long long*)idx)[e];
        d = (int)((const long long*)idx)[(long long)EE + e];
    } else {
        s = ((const int*)idx)[e];
        d = ((const int*)idx)[EE + e];
    }
    g_src[e] = s;
    g_dst[e] = d;
    atomicAdd(&g_pre[d], 1);
}
__global__ void scanfused_k() {
    int t = threadIdx.x, b = blockIdx.x;
    if (b == 0) { g_bnsum[t] = 0.f; g_bnsum[t + HC] = 0.f; }
    int i = b * 256 + t;
    int v = (i < NN) ? g_pre[i] : 0;
    int lane = t & 31, w = t >> 5;
    int x = v;
    #pragma unroll
    for (int d = 1; d < 32; d <<= 1) {
        int y = __shfl_up_sync(0xFFFFFFFFu, x, d);
        if (lane >= d) x += y;
    }
    __shared__ int ws[8];
    __shared__ int s_off;
    if (lane == 31) ws[w] = x;
    __syncthreads();
    if (t == 0) {
        int s = 0;
        #pragma unroll
        for (int j = 0; j < 8; j++) { s += ws[j]; ws[j] = s; }
        int total = s;
        int* part = g_pre + NN;
        int* pref = g_pre + NN + SCB;
        atomicExch(&part[b], total + 1);
        int run = 0;
        for (int j = b - 1; j >= 0;) {
            int pf = atomicAdd(&pref[j], 0);
            if (pf) { run += pf - 1; break; }
            int pt = atomicAdd(&part[j], 0);
            if (pt) { run += pt - 1; j--; }
        }
        atomicExch(&pref[b], run + total + 1);
        s_off = run;
    }
    __syncthreads();
    int incl = x + (w ? ws[w - 1] : 0);
    int off = s_off;
    if (i < NN) {
        int ex = off + incl - v;
        g_rowstart[i] = ex;
        g_cursor[i] = ex;
    }
    if (i == 0) g_rowstart[NN] = EE;
}
__global__ void fill_k() {
    int e = blockIdx.x * blockDim.x + threadIdx.x;
    if (e >= EE) return;
    int pos = atomicAdd(&g_cursor[g_dst[e]], 1);
    g_csr_src[pos] = g_src[e];
}

// ---------------- weight transpose + bf16 split (W1 alone; W2+W3 together) ----------------
__global__ void wconv1_k(const float* __restrict__ W1) {
    int idx = blockIdx.x * blockDim.x + threadIdx.x;
    if (idx >= FIN * HC) return;
    int k = idx / HC, n = idx % HC;
    float v = W1[idx];
    __nv_bfloat16 h = __float2bfloat16_rn(v);
    g_w1t_hi[(size_t)n * FIN + k] = h;
    g_w1t_lo[(size_t)n * FIN + k] = __float2bfloat16_rn(v - __bfloat162float(h));
}
__global__ void wconv23_k(const float* __restrict__ W2, const float* __restrict__ W3) {
    int gid = blockIdx.x * blockDim.x + threadIdx.x;
    const float* W;
    __nv_bfloat16 *Thi, *Tlo;
    int K, N, idx;
    if (gid < HC * HC) {
        W = W2; Thi = g_w2t_hi; Tlo = g_w2t_lo; K = HC; N = HC; idx = gid;
    } else if (gid < HC * HC + HC * OUTC) {
        W = W3; Thi = g_w3t_hi; Tlo = g_w3t_lo; K = HC; N = OUTC; idx = gid - HC * HC;
    } else return;
    int k = idx / N, n = idx % N;
    float v = W[idx];
    __nv_bfloat16 h = __float2bfloat16_rn(v);
    Thi[(size_t)n * K + k] = h;
    Tlo[(size_t)n * K + k] = __float2bfloat16_rn(v - __bfloat162float(h));
}

// ---------------- pipelined mma.sync split-bf16 GEMM (+ fused attention scores) ----------------
template <int KT, int NT, int NTILE, int WARPS_N, int JK, int SCORES>
__global__ __launch_bounds__(128 * WARPS_N, 2)
void mma_gemm_k(const float* __restrict__ A, const float* __restrict__ A2,
                const __nv_bfloat16* __restrict__ Bhi, const __nv_bfloat16* __restrict__ Blo,
                const float* __restrict__ bias, float* __restrict__ C,
                const float* __restrict__ asrc, const float* __restrict__ adst, int M) {
    constexpr int THREADS = 128 * WARPS_N;
    constexpr int WN = NTILE / WARPS_N;
    constexpr int NI = WN / 8;
    constexpr int LDA = 1024 / THREADS;
    constexpr int LDB = 8 * NTILE / THREADS;
    constexpr int CH = KT / 32;
    constexpr unsigned ABUF = 20480;
    constexpr unsigned BOFF = 2 * ABUF;
    constexpr unsigned BBUF = NTILE * 160;

    extern __shared__ char dynsm[];
    unsigned sbase = smem_u32(dynsm);
    int tid = threadIdx.x, lane = tid & 31, wid = tid >> 5;
    int wr = wid & 3, wc = wid >> 2;
    int rowBase = blockIdx.y * 128;
    int colBase = blockIdx.x * NTILE;
    float acc[2][NI][4] = {};
    float4 av[LDA], av2[LDA];

    auto loadA = [&](int c) {
        #pragma unroll
        for (int i = 0; i < LDA; i++) {
            int q = tid + i * THREADS;
            int r = q >> 3, cc = (q & 7) * 4;
            int grow = rowBase + r;
            av[i] = make_float4(0.f, 0.f, 0.f, 0.f);
            av2[i] = make_float4(0.f, 0.f, 0.f, 0.f);
            if (grow < M) {
                av[i] = *(const float4*)(A + (size_t)grow * KT + c * 32 + cc);
                if (JK) av2[i] = *(const float4*)(A2 + (size_t)grow * KT + c * 32 + cc);
            }
        }
    };
    auto storeA = [&](int buf) {
        #pragma unroll
        for (int i = 0; i < LDA; i++) {
            int q = tid + i * THREADS;
            int r = q >> 3, cc = (q & 7) * 4;
            float4 v = av[i];
            if (JK) {
                float4 w = av2[i];
                v.x = fmaxf(v.x, w.x); v.y = fmaxf(v.y, w.y);
                v.z = fmaxf(v.z, w.z); v.w = fmaxf(v.w, w.w);
            }
            float hx = __bfloat162float(__float2bfloat16_rn(v.x));
            float hy = __bfloat162float(__float2bfloat16_rn(v.y));
            float hz = __bfloat162float(__float2bfloat16_rn(v.z));
            float hw = __bfloat162float(__float2bfloat16_rn(v.w));
            unsigned off = buf * ABUF + (unsigned)(r * 40 + cc) * 2;
            *(uint2*)(dynsm + off) = make_uint2(pack2(hx, hy), pack2(hz, hw));
            *(uint2*)(dynsm + off + 10240) =
                make_uint2(pack2(v.x - hx, v.y - hy), pack2(v.z - hz, v.w - hw));
        }
    };
    auto loadB = [&](int c, int buf) {
        #pragma unroll
        for (int i = 0; i < LDB; i++) {
            int q = tid + i * THREADS;
            int hl = q / (4 * NTILE);
            int rem = q - hl * 4 * NTILE;
            int r = rem >> 2, seg = rem & 3;
            const __nv_bfloat16* src = hl ? Blo : Bhi;
            unsigned soff = BOFF + buf * BBUF + hl * (NTILE * 80) +
                            (unsigned)(r * 80 + seg * 16);
            cp16(sbase + soff, src + (size_t)(colBase + r) * KT + c * 32 + seg * 8);
        }
        asm volatile("cp.async.commit_group;");
    };
    auto compute = [&](int buf) {
        unsigned saA = sbase + buf * ABUF;
        unsigned saB = sbase + BOFF + buf * BBUF;
        #pragma unroll
        for (int kk = 0; kk < 32; kk += 16) {
            unsigned ah[2][4], al[2][4], bh[NI / 2][4], bl[NI / 2][4];
            #pragma unroll
            for (int mi = 0; mi < 2; mi++) {
                int row = wr * 32 + mi * 16 + (lane & 7) + ((lane & 8) ? 8 : 0);
                int col = kk + ((lane & 16) ? 8 : 0);
                ldsm4(ah[mi], saA + (unsigned)(row * 40 + col) * 2);
                ldsm4(al[mi], saA + 10240 + (unsigned)(row * 40 + col) * 2);
            }
            #pragma unroll
            for (int nb = 0; nb < NI / 2; nb++) {
                int row = wc * WN + nb * 16 + ((lane & 16) ? 8 : 0) + (lane & 7);
                int col = kk + ((lane & 8) ? 8 : 0);
                ldsm4(bh[nb], saB + (unsigned)(row * 40 + col) * 2);
                ldsm4(bl[nb], saB + (unsigned)(NTILE * 80) + (unsigned)(row * 40 + col) * 2);
            }
            #pragma unroll
            for (int mi = 0; mi < 2; mi++)
                #pragma unroll
                for (int nb = 0; nb < NI / 2; nb++) {
                    mma16816(acc[mi][2 * nb], ah[mi], &bh[nb][0]);
                    mma16816(acc[mi][2 * nb], ah[mi], &bl[nb][0]);
                    mma16816(acc[mi][2 * nb], al[mi], &bh[nb][0]);
                    mma16816(acc[mi][2 * nb + 1], ah[mi], &bh[nb][2]);
                    mma16816(acc[mi][2 * nb + 1], ah[mi], &bl[nb][2]);
                    mma16816(acc[mi][2 * nb + 1], al[mi], &bh[nb][2]);
                }
        }
    };

    loadB(0, 0);
    loadA(0);
    storeA(0);
    asm volatile("cp.async.wait_group 0;");
    __syncthreads();
    for (int c = 0; c < CH; c++) {
        int buf = c & 1;
        if (c + 1 < CH) { loadB(c + 1, buf ^ 1); loadA(c + 1); }
        compute(buf);
        if (c + 1 < CH) {
            storeA(buf ^ 1);
            asm volatile("cp.async.wait_group 0;");
        }
        __syncthreads();
    }
    #pragma unroll
    for (int mi = 0; mi < 2; mi++) {
        int grow0 = rowBase + wr * 32 + mi * 16 + (lane >> 2);
        int grow1 = grow0 + 8;
        #pragma unroll
        for (int ni = 0; ni < NI; ni++) {
            int gcol = colBase + wc * WN + ni * 8 + (lane & 3) * 2;
            float2 v0 = make_float2(acc[mi][ni][0], acc[mi][ni][1]);
            float2 v1 = make_float2(acc[mi][ni][2], acc[mi][ni][3]);
            if (JK) {
                float b0 = bias[gcol], b1 = bias[gcol + 1];
                v0.x += b0; v0.y += b1; v1.x += b0; v1.y += b1;
            }
            if (grow0 < M) *(float2*)(C + (size_t)grow0 * NT + gcol) = v0;
            if (grow1 < M) *(float2*)(C + (size_t)grow1 * NT + gcol) = v1;
        }
    }
    if (SCORES) {
        int head = (colBase >> 6) + wc;
        float as[NI][2], ad[NI][2];
        #pragma unroll
        for (int ni = 0; ni < NI; ni++) {
            int c = colBase + wc * WN + ni * 8 + (lane & 3) * 2;
            as[ni][0] = asrc[c]; as[ni][1] = asrc[c + 1];
            ad[ni][0] = adst[c]; ad[ni][1] = adst[c + 1];
        }
        #pragma unroll
        for (int mi = 0; mi < 2; mi++) {
            float e0 = 0.f, e1 = 0.f, d0 = 0.f, d1 = 0.f;
            #pragma unroll
            for (int ni = 0; ni < NI; ni++) {
                e0 = fmaf(acc[mi][ni][0], as[ni][0], e0);
                e0 = fmaf(acc[mi][ni][1], as[ni][1], e0);
                e1 = fmaf(acc[mi][ni][2], as[ni][0], e1);
                e1 = fmaf(acc[mi][ni][3], as[ni][1], e1);
                d0 = fmaf(acc[mi][ni][0], ad[ni][0], d0);
                d0 = fmaf(acc[mi][ni][1], ad[ni][1], d0);
                d1 = fmaf(acc[mi][ni][2], ad[ni][0], d1);
                d1 = fmaf(acc[mi][ni][3], ad[ni][1], d1);
            }
            e0 += __shfl_xor_sync(0xFFFFFFFFu, e0, 1); e0 += __shfl_xor_sync(0xFFFFFFFFu, e0, 2);
            e1 += __shfl_xor_sync(0xFFFFFFFFu, e1, 1); e1 += __shfl_xor_sync(0xFFFFFFFFu, e1, 2);
            d0 += __shfl_xor_sync(0xFFFFFFFFu, d0, 1); d0 += __shfl_xor_sync(0xFFFFFFFFu, d0, 2);
            d1 += __shfl_xor_sync(0xFFFFFFFFu, d1, 1); d1 += __shfl_xor_sync(0xFFFFFFFFu, d1, 2);
            if ((lane & 3) == 0) {
                int r0 = rowBase + wr * 32 + mi * 16 + (lane >> 2);
                int r1 = r0 + 8;
                if (r0 < M) { g_es[r0 * 4 + head] = e0; g_ed[r0 * 4 + head] = d0; }
                if (r1 < M) { g_es[r1 * 4 + head] = e1; g_ed[r1 * 4 + head] = d1; }
            }
        }
    }
}

// ---------------- fused softmax + aggregate (+BN stats): warp per node ----------------
template <int BN>
__global__ __launch_bounds__(256)
void softagg_k(const float* __restrict__ hfeat, const float* __restrict__ bias,
               float* __restrict__ out) {
    __shared__ float sal[8][32][4];
    int t = threadIdx.x, wid = t >> 5, lane = t & 31;
    int n = blockIdx.x * 8 + wid;
    int s = g_rowstart[n], en = g_rowstart[n + 1];
    int deg = en - s;
    bool small = (deg <= 32);
    int srcl = 0;

    if (deg > 0) {
        float4 ed = *(const float4*)&g_ed[n * 4];
        if (small) {
            float v0 = -1e30f, v1 = -1e30f, v2 = -1e30f, v3 = -1e30f;
            if (lane < deg) {
                srcl = g_csr_src[s + lane];
                float4 es = *(const float4*)&g_es[srcl * 4];
                v0 = es.x + ed.x; v0 = fmaxf(v0, 0.2f * v0);
                v1 = es.y + ed.y; v1 = fmaxf(v1, 0.2f * v1);
                v2 = es.z + ed.z; v2 = fmaxf(v2, 0.2f * v2);
                v3 = es.w + ed.w; v3 = fmaxf(v3, 0.2f * v3);
            }
            float m0 = v0, m1 = v1, m2 = v2, m3 = v3;
            #pragma unroll
            for (int o = 16; o > 0; o >>= 1) {
                m0 = fmaxf(m0, __shfl_xor_sync(0xFFFFFFFFu, m0, o));
                m1 = fmaxf(m1, __shfl_xor_sync(0xFFFFFFFFu, m1, o));
                m2 = fmaxf(m2, __shfl_xor_sync(0xFFFFFFFFu, m2, o));
                m3 = fmaxf(m3, __shfl_xor_sync(0xFFFFFFFFu, m3, o));
            }
            float p0 = 0.f, p1 = 0.f, p2 = 0.f, p3 = 0.f;
            if (lane < deg) {
                p0 = __expf(v0 - m0); p1 = __expf(v1 - m1);
                p2 = __expf(v2 - m2); p3 = __expf(v3 - m3);
            }
            float d0 = p0, d1 = p1, d2 = p2, d3 = p3;
            #pragma unroll
            for (int o = 16; o > 0; o >>= 1) {
                d0 += __shfl_xor_sync(0xFFFFFFFFu, d0, o);
                d1 += __shfl_xor_sync(0xFFFFFFFFu, d1, o);
                d2 += __shfl_xor_sync(0xFFFFFFFFu, d2, o);
                d3 += __shfl_xor_sync(0xFFFFFFFFu, d3, o);
            }
            if (lane < deg) {
                sal[wid][lane][0] = p0 / (d0 + 1e-16f);
                sal[wid][lane][1] = p1 / (d1 + 1e-16f);
                sal[wid][lane][2] = p2 / (d2 + 1e-16f);
                sal[wid][lane][3] = p3 / (d3 + 1e-16f);
            }
        } else {
            float m0 = -1e30f, m1 = -1e30f, m2 = -1e30f, m3 = -1e30f;
            for (int p = s + lane; p < en; p += 32) {
                int src = g_csr_src[p];
                float4 es = *(const float4*)&g_es[src * 4];
                float v0 = es.x + ed.x; v0 = fmaxf(v0, 0.2f * v0);
                float v1 = es.y + ed.y; v1 = fmaxf(v1, 0.2f * v1);
                float v2 = es.z + ed.z; v2 = fmaxf(v2, 0.2f * v2);
                float v3 = es.w + ed.w; v3 = fmaxf(v3, 0.2f * v3);
                m0 = fmaxf(m0, v0); m1 = fmaxf(m1, v1);
                m2 = fmaxf(m2, v2); m3 = fmaxf(m3, v3);
            }
            #pragma unroll
            for (int o = 16; o > 0; o >>= 1) {
                m0 = fmaxf(m0, __shfl_xor_sync(0xFFFFFFFFu, m0, o));
                m1 = fmaxf(m1, __shfl_xor_sync(0xFFFFFFFFu, m1, o));
                m2 = fmaxf(m2, __shfl_xor_sync(0xFFFFFFFFu, m2, o));
                m3 = fmaxf(m3, __shfl_xor_sync(0xFFFFFFFFu, m3, o));
            }
            float d0 = 0.f, d1 = 0.f, d2 = 0.f, d3 = 0.f;
            for (int p = s + lane; p < en; p += 32) {
                int src = g_csr_src[p];
                float4 es = *(const float4*)&g_es[src * 4];
                float v0 = es.x + ed.x; v0 = fmaxf(v0, 0.2f * v0);
                float v1 = es.y + ed.y; v1 = fmaxf(v1, 0.2f * v1);
                float v2 = es.z + ed.z; v2 = fmaxf(v2, 0.2f * v2);
                float v3 = es.w + ed.w; v3 = fmaxf(v3, 0.2f * v3);
                float4 a;
                a.x = __expf(v0 - m0); a.y = __expf(v1 - m1);
                a.z = __expf(v2 - m2); a.w = __expf(v3 - m3);
                d0 += a.x; d1 += a.y; d2 += a.z; d3 += a.w;
                *(float4*)&g_alpha[(size_t)p * 4] = a;
            }
            #pragma unroll
            for (int o = 16; o > 0; o >>= 1) {
                d0 += __shfl_xor_sync(0xFFFFFFFFu, d0, o);
                d1 += __shfl_xor_sync(0xFFFFFFFFu, d1, o);
                d2 += __shfl_xor_sync(0xFFFFFFFFu, d2, o);
                d3 += __shfl_xor_sync(0xFFFFFFFFu, d3, o);
            }
            float i0 = 1.f / (d0 + 1e-16f), i1 = 1.f / (d1 + 1e-16f);
            float i2 = 1.f / (d2 + 1e-16f), i3 = 1.f / (d3 + 1e-16f);
            for (int p = s + lane; p < en; p += 32) {
                float4 a = *(const float4*)&g_alpha[(size_t)p * 4];
                a.x *= i0; a.y *= i1; a.z *= i2; a.w *= i3;
                *(float4*)&g_alpha[(size_t)p * 4] = a;
            }
        }
    }
    __syncwarp();

    int h0 = lane >> 4, h1 = h0 + 2;
    int c0 = lane * 4, c1 = 128 + lane * 4;
    float4 A = {0, 0, 0, 0}, B = {0, 0, 0, 0};
    float4 A2 = {0, 0, 0, 0}, B2 = {0, 0, 0, 0};

    if (small) {
        int j = 0;
        for (; j + 4 <= deg; j += 4) {
            int s0 = __shfl_sync(0xFFFFFFFFu, srcl, j);
            int s1 = __shfl_sync(0xFFFFFFFFu, srcl, j + 1);
            int s2 = __shfl_sync(0xFFFFFFFFu, srcl, j + 2);
            int s3 = __shfl_sync(0xFFFFFFFFu, srcl, j + 3);
            float w0a = sal[wid][j][h0],     w0b = sal[wid][j][h1];
            float w1a = sal[wid][j + 1][h0], w1b = sal[wid][j + 1][h1];
            float w2a = sal[wid][j + 2][h0], w2b = sal[wid][j + 2][h1];
            float w3a = sal[wid][j + 3][h0], w3b = sal[wid][j + 3][h1];
            float4 f0a = *(const float4*)(hfeat + (size_t)s0 * HC + c0);
            float4 f0b = *(const float4*)(hfeat + (size_t)s0 * HC + c1);
            float4 f1a = *(const float4*)(hfeat + (size_t)s1 * HC + c0);
            float4 f1b = *(const float4*)(hfeat + (size_t)s1 * HC + c1);
            float4 f2a = *(const float4*)(hfeat + (size_t)s2 * HC + c0);
            float4 f2b = *(const float4*)(hfeat + (size_t)s2 * HC + c1);
            float4 f3a = *(const float4*)(hfeat + (size_t)s3 * HC + c0);
            float4 f3b = *(const float4*)(hfeat + (size_t)s3 * HC + c1);
            A.x = fmaf(w0a, f0a.x, A.x); A.y = fmaf(w0a, f0a.y, A.y);
            A.z = fmaf(w0a, f0a.z, A.z); A.w = fmaf(w0a, f0a.w, A.w);
            B.x = fmaf(w0b, f0b.x, B.x); B.y = fmaf(w0b, f0b.y, B.y);
            B.z = fmaf(w0b, f0b.z, B.z); B.w = fmaf(w0b, f0b.w, B.w);
            A2.x = fmaf(w1a, f1a.x, A2.x); A2.y = fmaf(w1a, f1a.y, A2.y);
            A2.z = fmaf(w1a, f1a.z, A2.z); A2.w = fmaf(w1a, f1a.w, A2.w);
            B2.x = fmaf(w1b, f1b.x, B2.x); B2.y = fmaf(w1b, f1b.y, B2.y);
            B2.z = fmaf(w1b, f1b.z, B2.z); B2.w = fmaf(w1b, f1b.w, B2.w);
            A.x = fmaf(w2a, f2a.x, A.x); A.y = fmaf(w2a, f2a.y, A.y);
            A.z = fmaf(w2a, f2a.z, A.z); A.w = fmaf(w2a, f2a.w, A.w);
            B.x = fmaf(w2b, f2b.x, B.x); B.y = fmaf(w2b, f2b.y, B.y);
            B.z = fmaf(w2b, f2b.z, B.z); B.w = fmaf(w2b, f2b.w, B.w);
            A2.x = fmaf(w3a, f3a.x, A2.x); A2.y = fmaf(w3a, f3a.y, A2.y);
            A2.z = fmaf(w3a, f3a.z, A2.z); A2.w = fmaf(w3a, f3a.w, A2.w);
            B2.x = fmaf(w3b, f3b.x, B2.x); B2.y = fmaf(w3b, f3b.y, B2.y);
            B2.z = fmaf(w3b, f3b.z, B2.z); B2.w = fmaf(w3b, f3b.w, B2.w);
        }
        for (; j < deg; j++) {
            int s0 = __shfl_sync(0xFFFFFFFFu, srcl, j);
            float wa = sal[wid][j][h0], wb = sal[wid][j][h1];
            float4 f0a = *(const float4*)(hfeat + (size_t)s0 * HC + c0);
            float4 f0b = *(const float4*)(hfeat + (size_t)s0 * HC + c1);
            A.x = fmaf(wa, f0a.x, A.x); A.y = fmaf(wa, f0a.y, A.y);
            A.z = fmaf(wa, f0a.z, A.z); A.w = fmaf(wa, f0a.w, A.w);
            B.x = fmaf(wb, f0b.x, B.x); B.y = fmaf(wb, f0b.y, B.y);
            B.z = fmaf(wb, f0b.z, B.z); B.w = fmaf(wb, f0b.w, B.w);
        }
    } else {
        int p = s;
        for (; p + 4 <= en; p += 4) {
            int s0 = g_csr_src[p], s1 = g_csr_src[p + 1];
            int s2 = g_csr_src[p + 2], s3 = g_csr_src[p + 3];
            float w0a = g_alpha[(size_t)p * 4 + h0],       w0b = g_alpha[(size_t)p * 4 + h1];
            float w1a = g_alpha[(size_t)(p + 1) * 4 + h0], w1b = g_alpha[(size_t)(p + 1) * 4 + h1];
            float w2a = g_alpha[(size_t)(p + 2) * 4 + h0], w2b = g_alpha[(size_t)(p + 2) * 4 + h1];
            float w3a = g_alpha[(size_t)(p + 3) * 4 + h0], w3b = g_alpha[(size_t)(p + 3) * 4 + h1];
            float4 f0a = *(const float4*)(hfeat + (size_t)s0 * HC + c0);
            float4 f0b = *(const float4*)(hfeat + (size_t)s0 * HC + c1);
            float4 f1a = *(const float4*)(hfeat + (size_t)s1 * HC + c0);
            float4 f1b = *(const float4*)(hfeat + (size_t)s1 * HC + c1);
            float4 f2a = *(const float4*)(hfeat + (size_t)s2 * HC + c0);
            float4 f2b = *(const float4*)(hfeat + (size_t)s2 * HC + c1);
            float4 f3a = *(const float4*)(hfeat + (size_t)s3 * HC + c0);
            float4 f3b = *(const float4*)(hfeat + (size_t)s3 * HC + c1);
            A.x = fmaf(w0a, f0a.x, A.x); A.y = fmaf(w0a, f0a.y, A.y);
            A.z = fmaf(w0a, f0a.z, A.z); A.w = fmaf(w0a, f0a.w, A.w);
            B.x = fmaf(w0b, f0b.x, B.x); B.y = fmaf(w0b, f0b.y, B.y);
            B.z = fmaf(w0b, f0b.z, B.z); B.w = fmaf(w0b, f0b.w, B.w);
            A2.x = fmaf(w1a, f1a.x, A2.x); A2.y = fmaf(w1a, f1a.y, A2.y);
            A2.z = fmaf(w1a, f1a.z, A2.z); A2.w = fmaf(w1a, f1a.w, A2.w);
            B2.x = fmaf(w1b, f1b.x, B2.x); B2.y = fmaf(w1b, f1b.y, B2.y);
            B2.z = fmaf(w1b, f1b.z, B2.z); B2.w = fmaf(w1b, f1b.w, B2.w);
            A.x = fmaf(w2a, f2a.x, A.x); A.y = fmaf(w2a, f2a.y, A.y);
            A.z = fmaf(w2a, f2a.z, A.z); A.w = fmaf(w2a, f2a.w, A.w);
            B.x = fmaf(w2b, f2b.x, B.x); B.y = fmaf(w2b, f2b.y, B.y);
            B.z = fmaf(w2b, f2b.z, B.z); B.w = fmaf(w2b, f2b.w, B.w);
            A2.x = fmaf(w3a, f3a.x, A2.x); A2.y = fmaf(w3a, f3a.y, A2.y);
            A2.z = fmaf(w3a, f3a.z, A2.z); A2.w = fmaf(w3a, f3a.w, A2.w);
            B2.x = fmaf(w3b, f3b.x, B2.x); B2.y = fmaf(w3b, f3b.y, B2.y);
            B2.z = fmaf(w3b, f3b.z, B2.z); B2.w = fmaf(w3b, f3b.w, B2.w);
        }
        for (; p < en; p++) {
            int s0 = g_csr_src[p];
            float wa = g_alpha[(size_t)p * 4 + h0], wb = g_alpha[(size_t)p * 4 + h1];
            float4 f0a = *(const float4*)(hfeat + (size_t)s0 * HC + c0);
            float4 f0b = *(const float4*)(hfeat + (size_t)s0 * HC + c1);
            A.x = fmaf(wa, f0a.x, A.x); A.y = fmaf(wa, f0a.y, A.y);
            A.z = fmaf(wa, f0a.z, A.z); A.w = fmaf(wa, f0a.w, A.w);
            B.x = fmaf(wb, f0b.x, B.x); B.y = fmaf(wb, f0b.y, B.y);
            B.z = fmaf(wb, f0b.z, B.z); B.w = fmaf(wb, f0b.w, B.w);
        }
    }
    float4 ba = *(const float4*)(bias + c0);
    float4 bb = *(const float4*)(bias + c1);
    float4 oa, ob;
    oa.x = A.x + A2.x + ba.x; oa.y = A.y + A2.y + ba.y;
    oa.z = A.z + A2.z + ba.z; oa.w = A.w + A2.w + ba.w;
    ob.x = B.x + B2.x + bb.x; ob.y = B.y + B2.y + bb.y;
    ob.z = B.z + B2.z + bb.z; ob.w = B.w + B2.w + bb.w;
    *(float4*)(out + (size_t)n * HC + c0) = oa;
    *(float4*)(out + (size_t)n * HC + c1) = ob;

    if (BN) {
        __syncthreads();
        sal[wid][lane][0] = oa.x; sal[wid][lane][1] = oa.y;
        sal[wid][lane][2] = oa.z; sal[wid][lane][3] = oa.w;
        __syncthreads();
        if (t < 128) {
            float sum = 0.f, sq = 0.f;
            #pragma unroll
            for (int w = 0; w < 8; w++) {
                float v = sal[w][t >> 2][t & 3];
                sum += v; sq += v * v;
            }
            atomicAdd(&g_bnsum[t], sum);
            atomicAdd(&g_bnsum[HC + t], sq);
        }
        __syncthreads();
        sal[wid][lane][0] = ob.x; sal[wid][lane][1] = ob.y;
        sal[wid][lane][2] = ob.z; sal[wid][lane][3] = ob.w;
        __syncthreads();
        if (t < 128) {
            float sum = 0.f, sq = 0.f;
            #pragma unroll
            for (int w = 0; w < 8; w++) {
                float v = sal[w][t >> 2][t & 3];
                sum += v; sq += v * v;
            }
            atomicAdd(&g_bnsum[128 + t], sum);
            atomicAdd(&g_bnsum[HC + 128 + t], sq);
        }
    }
}

// ---------------- BatchNorm apply (stats in g_bnsum) ----------------
__global__ __launch_bounds__(256)
void bn_apply_k(const float* __restrict__ x, const float* __restrict__ gamma,
                const float* __restrict__ beta, float* __restrict__ y) {
    __shared__ float ssc[HC], ssh[HC];
    int t = threadIdx.x;
    float mean = g_bnsum[t] / (float)NN;
    float var = g_bnsum[HC + t] / (float)NN - mean * mean;
    float sc = gamma[t] * rsqrtf(var + 1e-5f);
    ssc[t] = sc;
    ssh[t] = beta[t] - mean * sc;
    __syncthreads();
    for (long long i = blockIdx.x * 256 + t; i < (long long)NN * 64;
         i += (long long)gridDim.x * 256) {
        int ch = ((int)i & 63) * 4;
        float4 v = *(const float4*)(x + i * 4);
        v.x = v.x * ssc[ch] + ssh[ch];
        v.y = v.y * ssc[ch + 1] + ssh[ch + 1];
        v.z = v.z * ssc[ch + 2] + ssh[ch + 2];
        v.w = v.w * ssc[ch + 3] + ssh[ch + 3];
        v.x = (v.x > 0.f) ? v.x : expm1f(v.x);
        v.y = (v.y > 0.f) ? v.y : expm1f(v.y);
        v.z = (v.z > 0.f) ? v.z : expm1f(v.z);
        v.w = (v.w > 0.f) ? v.w : expm1f(v.w);
        *(float4*)(y + i * 4) = v;
    }
}

// ---------------- host ----------------
#define GDM ((NN + 127) / 128)
#define SMEM_128 (40960 + 2 * 128 * 160)   // 81920
#define SMEM_64  (40960 + 2 * 64 * 160)    // 61440

extern "C" void kernel_launch(void* const* d_in, const int* in_sizes, int n_in,
                              void* d_out, int out_size) {
    const float* x   = (const float*)d_in[0];
    const void*  eidx = d_in[1];
    const float* a1s = (const float*)d_in[3];
    const float* a1d = (const float*)d_in[4];
    const float* b1  = (const float*)d_in[5];
    const float* g1  = (const float*)d_in[6];
    const float* be1 = (const float*)d_in[7];
    const float* a2s = (const float*)d_in[9];
    const float* a2d = (const float*)d_in[10];
    const float* b2  = (const float*)d_in[11];
    const float* lb  = (const float*)d_in[13];
    float* out = (float*)d_out;

    float *ph, *pgat, *pl1, *pl2;
    cudaGetSymbolAddress((void**)&ph,   g_h);
    cudaGetSymbolAddress((void**)&pgat, g_gat);
    cudaGetSymbolAddress((void**)&pl1,  g_l1);
    cudaGetSymbolAddress((void**)&pl2,  g_l2);
    __nv_bfloat16 *w1h, *w1l, *w2h, *w2l, *w3h, *w3l;
    cudaGetSymbolAddress((void**)&w1h, g_w1t_hi);
    cudaGetSymbolAddress((void**)&w1l, g_w1t_lo);
    cudaGetSymbolAddress((void**)&w2h, g_w2t_hi);
    cudaGetSymbolAddress((void**)&w2l, g_w2t_lo);
    cudaGetSymbolAddress((void**)&w3h, g_w3t_hi);
    cudaGetSymbolAddress((void**)&w3l, g_w3t_lo);
    int* ppre;
    cudaGetSymbolAddress((void**)&ppre, g_pre);

    cudaFuncSetAttribute((const void*)mma_gemm_k<FIN, HC, 128, 2, 0, 1>,
                         cudaFuncAttributeMaxDynamicSharedMemorySize, SMEM_128);
    cudaFuncSetAttribute((const void*)mma_gemm_k<HC, HC, 128, 2, 0, 1>,
                         cudaFuncAttributeMaxDynamicSharedMemorySize, SMEM_128);
    cudaFuncSetAttribute((const void*)mma_gemm_k<HC, OUTC, 64, 2, 1, 0>,
                         cudaFuncAttributeMaxDynamicSharedMemorySize, SMEM_64);

    // fork-join: edge preprocessing + W2/W3 conversion run concurrently
    // with W1 conversion + gemm1 on the main stream
    cudaStream_t s2;
    cudaStreamCreateWithFlags(&s2, cudaStreamNonBlocking);
    cudaEvent_t evFork, evJoin;
    cudaEventCreateWithFlags(&evFork, cudaEventDisableTiming);
    cudaEventCreateWithFlags(&evJoin, cudaEventDisableTiming);

    cudaMemsetAsync(ppre, 0, (NN + 2 * SCB) * sizeof(int));
    cudaEventRecord(evFork, 0);
    cudaStreamWaitEvent(s2, evFork, 0);
    cvt_count_k<<<(EE + 255) / 256, 256, 0, s2>>>(eidx);
    scanfused_k<<<SCB, 256, 0, s2>>>();   // also zeroes g_bnsum
    fill_k<<<(EE + 255) / 256, 256, 0, s2>>>();
    wconv23_k<<<(HC * HC + HC * OUTC + 255) / 256, 256, 0, s2>>>(
        (const float*)d_in[8], (const float*)d_in[12]);
    cudaEventRecord(evJoin, s2);

    wconv1_k<<<(FIN * HC + 255) / 256, 256>>>((const float*)d_in[2]);
    {
        dim3 g(2, GDM);
        mma_gemm_k<FIN, HC, 128, 2, 0, 1><<<g, 256, SMEM_128>>>(
            x, nullptr, w1h, w1l, nullptr, ph, a1s, a1d, NN);
    }
    cudaStreamWaitEvent(0, evJoin, 0);

    softagg_k<1><<<NN / 8, 256>>>(ph, b1, pgat);
    bn_apply_k<<<592, 256>>>(pgat, g1, be1, pl1);

    {
        dim3 g(2, GDM);
        mma_gemm_k<HC, HC, 128, 2, 0, 1><<<g, 256, SMEM_128>>>(
            pl1, nullptr, w2h, w2l, nullptr, ph, a2s, a2d, NN);
    }
    softagg_k<0><<<NN / 8, 256>>>(ph, b2, pl2);

    {
        dim3 g(1, GDM);
        mma_gemm_k<HC, OUTC, 64, 2, 1, 0><<<g, 256, SMEM_64>>>(
            pl1, pl2, w3h, w3l, lb, out, nullptr, nullptr, NN);
    }
    // not destroying s2/events: destroying capture-participating objects
    // mid-capture is hazardous; kernel_launch is called O(1) times.
}